// round 13
// baseline (speedup 1.0000x reference)
#include <cuda_runtime.h>
#include <math.h>

#define NN 100000
#define NE 2000000
#define INC 30
#define HID 40
#define D1 20
#define D2 10
#define NCLS 3
#define NB_SP 128   // softpool blocks
#define NB_TK 128   // topk stage-1 blocks
#define NB_EDGE ((NE + 255) / 256)   // 7813
#define NB_NODE ((NN + 255) / 256)   // 391
#define CSR_CAP (NE + 3 * NN)

// out layout: logits[3], Y_prob[3], Y_hat[1], A[NN], x3[NN*D1], cell_loss[1]
#define OUT_A 7
#define OUT_X3 (7 + NN)
#define OUT_LOSS (7 + NN + NN * D1)

// ---------------- scratch ----------------
__device__ __align__(16) float g_h[NN * HID];
__device__ __align__(16) float g_agg[NN * HID];
__device__ __align__(16) float g_x3[NN * D1];
__device__ float g_a[NN];
__device__ unsigned long long g_dc[NN];    // packed cnt<<40 | deg*2^28 (zero on entry; re-zeroed in scan3)
__device__ float g_dinv[NN];
__device__ int   g_pref[NN];
__device__ int   g_bsum[128];
__device__ int   g_rowstart[NN + 1];       // padded rowstarts (multiple-of-3 lists)
__device__ unsigned long long g_sdr[NE];   // packed s | d<<17 | rank<<34
__device__ unsigned long long g_csr[CSR_CAP];
__device__ float g_bm[NB_SP];
__device__ float g_bs[NB_SP];
__device__ float g_bp[NB_SP * D1];
__device__ float g_gmax;
__device__ float g_denom;
__device__ float g_pooled[D1];
__device__ float g_cand_v[2 * NB_TK * 8];
__device__ int   g_cand_i[2 * NB_TK * 8];
__device__ unsigned int g_done;            // zero on entry; re-zeroed in topk2

// ---------------- helpers ----------------
__device__ __forceinline__ float selu_f(float x) {
    const float sc = 1.0507009873554805f, al = 1.6732632423543772f;
    return x > 0.f ? sc * x : sc * al * expm1f(x);
}
__device__ __forceinline__ int clampn(int v) {
    return v < 0 ? 0 : (v >= NN ? NN - 1 : v);
}

// ---------------- kernels ----------------
// blocks [0, NB_EDGE): edge prep (single packed atomic, write (s,d,rank))
// blocks [NB_EDGE, NB_EDGE+NB_NODE): h = x @ W1
__global__ void k_prepmm(const void* __restrict__ eiv, const float* __restrict__ ew,
                         const float* __restrict__ X, const float* __restrict__ W) {
    if (blockIdx.x < NB_EDGE) {
        __shared__ int any_nz;
        const int* ei32 = (const int*)eiv;
        if (threadIdx.x == 0) any_nz = 0;
        __syncthreads();
        if (ei32[2 * threadIdx.x + 1] != 0) atomicOr(&any_nz, 1);
        __syncthreads();
        bool is64 = (any_nz == 0);
        int e = blockIdx.x * 256 + threadIdx.x;
        if (e >= NE) return;
        int s, d;
        if (is64) {
            const long long* ei = (const long long*)eiv;
            s = (int)ei[e]; d = (int)ei[NE + e];
        } else {
            s = ei32[e]; d = ei32[NE + e];
        }
        s = clampn(s); d = clampn(d);
        unsigned long long fx = (unsigned long long)(ew[e] * 268435456.0f + 0.5f);
        unsigned long long old = atomicAdd(&g_dc[d], (1ULL << 40) | fx);
        unsigned long long rank = old >> 40;
        g_sdr[e] = (unsigned long long)(unsigned)s |
                   ((unsigned long long)(unsigned)d << 17) | (rank << 34);
    } else {
        __shared__ float sW[INC * HID];
        for (int i = threadIdx.x; i < INC * HID; i += 256) sW[i] = W[i];
        __syncthreads();
        int n = (blockIdx.x - NB_EDGE) * 256 + threadIdx.x;
        if (n >= NN) return;
        float acc[HID];
#pragma unroll
        for (int o = 0; o < HID; o++) acc[o] = 0.f;
        const float* xr = X + (long)n * INC;
#pragma unroll
        for (int k = 0; k < INC; k++) {
            float xv = __ldg(xr + k);
#pragma unroll
            for (int o = 0; o < HID; o++) acc[o] += xv * sW[k * HID + o];
        }
        float* yr = g_h + (long)n * HID;
#pragma unroll
        for (int o = 0; o < HID; o++) yr[o] = acc[o];
    }
}

// block-local exclusive scan of PADDED counts (multiple of 3)
__global__ void k_scan1() {
    __shared__ int sm[1024];
    int t = threadIdx.x;
    int gid = blockIdx.x * 1024 + t;
    int pc = 0;
    if (gid < NN) {
        int c = (int)(g_dc[gid] >> 40);
        pc = ((c + 2) / 3) * 3;
    }
    sm[t] = pc; __syncthreads();
    for (int off = 1; off < 1024; off <<= 1) {
        int v = (t >= off) ? sm[t - off] : 0;
        __syncthreads();
        sm[t] += v;
        __syncthreads();
    }
    if (gid < NN) g_pref[gid] = sm[t] - pc;
    if (t == 1023) g_bsum[blockIdx.x] = sm[1023];
}

// add block offsets + rowstart/dinv; write zero-weight pad entries; reset g_dc
__global__ void k_scan3(int nblk) {
    __shared__ int sb[128];
    __shared__ int soff;
    int t = threadIdx.x;
    if (t < 128) sb[t] = (t < nblk) ? g_bsum[t] : 0;
    __syncthreads();
    if (t == 0) {
        int s = 0;
        for (int j = 0; j < blockIdx.x; j++) s += sb[j];
        soff = s;
    }
    __syncthreads();
    int gid = blockIdx.x * 1024 + t;
    if (gid < NN) {
        int rs = g_pref[gid] + soff;
        g_rowstart[gid] = rs;
        unsigned long long dc = g_dc[gid];
        int c = (int)(dc >> 40);
        int pc = ((c + 2) / 3) * 3;
        float deg = (float)(dc & ((1ULL << 40) - 1ULL)) * (1.0f / 268435456.0f);
        g_dinv[gid] = rsqrtf(deg + 1.0f);
        g_dc[gid] = 0ULL;
        for (int j = c; j < pc; j++) g_csr[rs + j] = 0ULL;  // pad: s=0, w=0
        if (gid == NN - 1) g_rowstart[NN] = rs + pc;
    }
}

// build CSR entries (src, norm) — no atomics, position = rowstart[d] + rank
__global__ void k_scatter(const float* __restrict__ ew) {
    int e = blockIdx.x * 256 + threadIdx.x;
    if (e >= NE) return;
    unsigned long long ent = __ldg(&g_sdr[e]);
    int s = (int)(ent & 0x1FFFFULL);
    int d = (int)((ent >> 17) & 0x1FFFFULL);
    int rank = (int)(ent >> 34);
    float w = g_dinv[s] * __ldg(ew + e) * g_dinv[d];
    int pos = g_rowstart[d] + rank;
    g_csr[pos] = ((unsigned long long)__float_as_uint(w) << 32) | (unsigned int)s;
}

// CSR aggregation: warp per node, 30 lanes = 3 edges x 10 chunks.
// Padded (multiple-of-3) lists: predicate-free inner loop WITH csr prefetch.
// agg[n] = sum_e w_e * h[src_e] + h[n]*dinv[n]^2 + b
__global__ void k_aggc(const float* __restrict__ b) {
    int warp = blockIdx.x * 8 + (threadIdx.x >> 5);
    if (warp >= NN) return;
    int lane = threadIdx.x & 31;
    int grp = lane / 10;          // 0..2 active, 3 idle (lanes 30,31)
    int chunk = lane - grp * 10;  // 0..9
    int beg = g_rowstart[warp], end = g_rowstart[warp + 1];
    const float4* h4 = reinterpret_cast<const float4*>(g_h);
    float4 acc = make_float4(0.f, 0.f, 0.f, 0.f);
    if (lane < 30 && beg < end) {
        int e = beg + grp;
        unsigned long long ent = __ldg(&g_csr[e]);
        for (e += 3; e < end; e += 3) {
            unsigned long long cur = ent;
            ent = __ldg(&g_csr[e]);
            int s = (int)(unsigned int)cur;
            float w = __uint_as_float((unsigned int)(cur >> 32));
            float4 v = __ldg(h4 + s * 10 + chunk);
            acc.x += v.x * w; acc.y += v.y * w;
            acc.z += v.z * w; acc.w += v.w * w;
        }
        int s = (int)(unsigned int)ent;
        float w = __uint_as_float((unsigned int)(ent >> 32));
        float4 v = __ldg(h4 + s * 10 + chunk);
        acc.x += v.x * w; acc.y += v.y * w;
        acc.z += v.z * w; acc.w += v.w * w;
    }
    float rx = acc.x + __shfl_down_sync(0xffffffffu, acc.x, 10)
                     + __shfl_down_sync(0xffffffffu, acc.x, 20);
    float ry = acc.y + __shfl_down_sync(0xffffffffu, acc.y, 10)
                     + __shfl_down_sync(0xffffffffu, acc.y, 20);
    float rz = acc.z + __shfl_down_sync(0xffffffffu, acc.z, 10)
                     + __shfl_down_sync(0xffffffffu, acc.z, 20);
    float rw = acc.w + __shfl_down_sync(0xffffffffu, acc.w, 10)
                     + __shfl_down_sync(0xffffffffu, acc.w, 20);
    if (lane < 10) {
        float di = g_dinv[warp], d2 = di * di;
        float4 hv = h4[warp * 10 + lane];
        float4 bv = __ldg(reinterpret_cast<const float4*>(b) + lane);
        float4 r;
        r.x = rx + hv.x * d2 + bv.x;
        r.y = ry + hv.y * d2 + bv.y;
        r.z = rz + hv.z * d2 + bv.z;
        r.w = rw + hv.w * d2 + bv.w;
        reinterpret_cast<float4*>(g_agg)[warp * 10 + lane] = r;
    }
}

// x1 = selu(ln(agg)); h2 = x1 @ W2 -> g_h (overwrite)
__global__ void k_post1mm(const float* __restrict__ lw, const float* __restrict__ lb,
                          const float* __restrict__ W2) {
    __shared__ float sW[HID * HID];
    for (int i = threadIdx.x; i < HID * HID; i += blockDim.x) sW[i] = W2[i];
    __syncthreads();
    int n = blockIdx.x * blockDim.x + threadIdx.x;
    if (n >= NN) return;
    float v[HID];
    const float4* ag = reinterpret_cast<const float4*>(g_agg) + n * (HID / 4);
    float s = 0.f;
#pragma unroll
    for (int j = 0; j < HID / 4; j++) {
        float4 a4 = ag[j];
        v[4 * j + 0] = a4.x; v[4 * j + 1] = a4.y;
        v[4 * j + 2] = a4.z; v[4 * j + 3] = a4.w;
        s += a4.x + a4.y + a4.z + a4.w;
    }
    float m = s * (1.f / HID);
    float vs = 0.f;
#pragma unroll
    for (int f = 0; f < HID; f++) { float dd = v[f] - m; vs += dd * dd; }
    float inv = rsqrtf(vs * (1.f / HID) + 1e-5f);
#pragma unroll
    for (int f = 0; f < HID; f++)
        v[f] = selu_f((v[f] - m) * inv * __ldg(lw + f) + __ldg(lb + f));
    float acc[HID];
#pragma unroll
    for (int o = 0; o < HID; o++) acc[o] = 0.f;
#pragma unroll
    for (int k = 0; k < HID; k++) {
        float xv = v[k];
#pragma unroll
        for (int o = 0; o < HID; o++) acc[o] += xv * sW[k * HID + o];
    }
    float* yr = g_h + (long)n * HID;
#pragma unroll
    for (int o = 0; o < HID; o++) yr[o] = acc[o];
}

// x2 = selu(ln(agg)); x3 = selu(x2@Wf+bf) -> g_x3 + outx3; a = attention score
__global__ void k_post2(const float* __restrict__ lw, const float* __restrict__ lb,
                        const float* __restrict__ Wf, const float* __restrict__ bf,
                        const float* __restrict__ Wt, const float* __restrict__ bt,
                        const float* __restrict__ Ws, const float* __restrict__ bs,
                        const float* __restrict__ Wc, const float* __restrict__ bc,
                        float* __restrict__ outx3) {
    __shared__ float sWf[HID * D1];
    __shared__ float sWt[D1 * D2];
    __shared__ float sWs[D1 * D2];
    __shared__ float sWc[D2];
    __shared__ float sbf[D1], sbt[D2], sbs[D2];
    int t = threadIdx.x;
    for (int i = t; i < HID * D1; i += blockDim.x) sWf[i] = Wf[i];
    for (int i = t; i < D1 * D2; i += blockDim.x) { sWt[i] = Wt[i]; sWs[i] = Ws[i]; }
    if (t < D2) { sWc[t] = Wc[t]; sbt[t] = bt[t]; sbs[t] = bs[t]; }
    if (t < D1) sbf[t] = bf[t];
    __syncthreads();
    int n = blockIdx.x * blockDim.x + t;
    if (n >= NN) return;
    float v[HID];
    const float4* ag = reinterpret_cast<const float4*>(g_agg) + n * (HID / 4);
    float s = 0.f;
#pragma unroll
    for (int j = 0; j < HID / 4; j++) {
        float4 a4 = ag[j];
        v[4 * j + 0] = a4.x; v[4 * j + 1] = a4.y;
        v[4 * j + 2] = a4.z; v[4 * j + 3] = a4.w;
        s += a4.x + a4.y + a4.z + a4.w;
    }
    float m = s * (1.f / HID);
    float vs = 0.f;
#pragma unroll
    for (int f = 0; f < HID; f++) { float dd = v[f] - m; vs += dd * dd; }
    float inv = rsqrtf(vs * (1.f / HID) + 1e-5f);
#pragma unroll
    for (int f = 0; f < HID; f++)
        v[f] = selu_f((v[f] - m) * inv * __ldg(lw + f) + __ldg(lb + f));
    float x3[D1];
#pragma unroll
    for (int o = 0; o < D1; o++) {
        float acc = sbf[o];
#pragma unroll
        for (int k = 0; k < HID; k++) acc += v[k] * sWf[k * D1 + o];
        x3[o] = selu_f(acc);
    }
    float* xo = g_x3 + (long)n * D1;
    float* xo2 = outx3 + (long)n * D1;
#pragma unroll
    for (int o = 0; o < D1; o++) { xo[o] = x3[o]; xo2[o] = x3[o]; }
    float a = __ldg(bc);
#pragma unroll
    for (int j = 0; j < D2; j++) {
        float zt = sbt[j], zs = sbs[j];
#pragma unroll
        for (int k = 0; k < D1; k++) { zt += x3[k] * sWt[k * D2 + j]; zs += x3[k] * sWs[k * D2 + j]; }
        a += tanhf(zt) * (1.f / (1.f + expf(-zs))) * sWc[j];
    }
    g_a[n] = a;
}

// per-block (m, s, p) partials; last block finalizes gmax/denom/pooled
__global__ void k_softpool() {
    __shared__ float sm[256];
    __shared__ float sbp[D1];
    __shared__ bool isLast;
    int t = threadIdx.x;
    float mx = __int_as_float(0xff800000);
    for (int i = blockIdx.x * 256 + t; i < NN; i += NB_SP * 256)
        mx = fmaxf(mx, g_a[i]);
    sm[t] = mx; __syncthreads();
    for (int st = 128; st > 0; st >>= 1) {
        if (t < st) sm[t] = fmaxf(sm[t], sm[t + st]);
        __syncthreads();
    }
    float mb = sm[0];
    __syncthreads();
    float ssum = 0.f;
    float acc[D1];
#pragma unroll
    for (int f = 0; f < D1; f++) acc[f] = 0.f;
    for (int i = blockIdx.x * 256 + t; i < NN; i += NB_SP * 256) {
        float w = expf(g_a[i] - mb);
        ssum += w;
        const float4* xr = reinterpret_cast<const float4*>(g_x3) + i * (D1 / 4);
#pragma unroll
        for (int j = 0; j < D1 / 4; j++) {
            float4 t4 = __ldg(xr + j);
            acc[4 * j + 0] += w * t4.x; acc[4 * j + 1] += w * t4.y;
            acc[4 * j + 2] += w * t4.z; acc[4 * j + 3] += w * t4.w;
        }
    }
    sm[t] = ssum; __syncthreads();
    for (int st = 128; st > 0; st >>= 1) {
        if (t < st) sm[t] += sm[t + st];
        __syncthreads();
    }
    if (t == 0) { g_bm[blockIdx.x] = mb; g_bs[blockIdx.x] = sm[0]; }
    if (t < D1) sbp[t] = 0.f;
    __syncthreads();
#pragma unroll
    for (int f = 0; f < D1; f++) {
        float vv = acc[f];
        for (int off = 16; off; off >>= 1) vv += __shfl_down_sync(0xffffffffu, vv, off);
        if ((t & 31) == 0) atomicAdd(&sbp[f], vv);
    }
    __syncthreads();
    if (t < D1) g_bp[blockIdx.x * D1 + t] = sbp[t];
    __threadfence();
    if (t == 0) {
        unsigned int prev = atomicAdd(&g_done, 1u);
        isLast = (prev == NB_SP - 1);
    }
    __syncthreads();
    if (!isLast) return;
    __threadfence();
    float mt = (t < NB_SP) ? g_bm[t] : __int_as_float(0xff800000);
    sm[t] = mt; __syncthreads();
    for (int st = 128; st > 0; st >>= 1) {
        if (t < st) sm[t] = fmaxf(sm[t], sm[t + st]);
        __syncthreads();
    }
    float M = sm[0];
    __syncthreads();
    float scale = (t < NB_SP) ? expf(mt - M) : 0.f;
    sm[t] = (t < NB_SP) ? g_bs[t] * scale : 0.f;
    __syncthreads();
    for (int st = 128; st > 0; st >>= 1) {
        if (t < st) sm[t] += sm[t + st];
        __syncthreads();
    }
    float denom = sm[0];
    if (t == 0) { g_gmax = M; g_denom = denom; }
    __syncthreads();
    for (int f = 0; f < D1; f++) {
        sm[t] = (t < NB_SP) ? g_bp[t * D1 + f] * scale : 0.f;
        __syncthreads();
        for (int st = 128; st > 0; st >>= 1) {
            if (t < st) sm[t] += sm[t + st];
            __syncthreads();
        }
        if (t == 0) g_pooled[f] = sm[0] / denom;
        __syncthreads();
    }
}

// stage-1 topk: each block = 1024 contiguous elements; also writes softmax A
__global__ void k_topk1(float* __restrict__ outA) {
    __shared__ float sv[1024];
    __shared__ int si[1024];
    int t = threadIdx.x;
    int gid = blockIdx.x * 1024 + t;
    bool valid = gid < NN;
    float a = valid ? g_a[gid] : 0.f;
    if (valid) outA[gid] = expf(a - g_gmax) / g_denom;
    float vt = valid ? a : __int_as_float(0xff800000);
    float vb = valid ? a : __int_as_float(0x7f800000);
    int myi = valid ? gid : 0x7fffffff;
    for (int pass = 0; pass < 8; pass++) {
        sv[t] = vt; si[t] = myi; __syncthreads();
        for (int st = 512; st > 0; st >>= 1) {
            if (t < st) {
                float v2 = sv[t + st]; int i2 = si[t + st];
                if (v2 > sv[t] || (v2 == sv[t] && i2 < si[t])) { sv[t] = v2; si[t] = i2; }
            }
            __syncthreads();
        }
        if (t == 0) {
            g_cand_v[blockIdx.x * 8 + pass] = sv[0];
            g_cand_i[blockIdx.x * 8 + pass] = si[0];
        }
        if (myi == si[0]) vt = __int_as_float(0xff800000);
        __syncthreads();
    }
    for (int pass = 0; pass < 8; pass++) {
        sv[t] = vb; si[t] = myi; __syncthreads();
        for (int st = 512; st > 0; st >>= 1) {
            if (t < st) {
                float v2 = sv[t + st]; int i2 = si[t + st];
                if (v2 < sv[t] || (v2 == sv[t] && i2 < si[t])) { sv[t] = v2; si[t] = i2; }
            }
            __syncthreads();
        }
        if (t == 0) {
            g_cand_v[NB_TK * 8 + blockIdx.x * 8 + pass] = sv[0];
            g_cand_i[NB_TK * 8 + blockIdx.x * 8 + pass] = si[0];
        }
        if (myi == si[0]) vb = __int_as_float(0x7f800000);
        __syncthreads();
    }
}

// stage-2 merge + final tail math; resets g_done for next replay
__global__ void k_topk2(const float* __restrict__ Wcls, const float* __restrict__ bcls,
                        const float* __restrict__ Wcell, const float* __restrict__ bcell,
                        const int* __restrict__ labelp, float* __restrict__ out) {
    __shared__ float sv[1024];
    __shared__ int si[1024];
    __shared__ int ssel[16];
    int t = threadIdx.x;
    float vt = g_cand_v[t];
    int it = g_cand_i[t];
    for (int pass = 0; pass < 8; pass++) {
        sv[t] = vt; si[t] = it; __syncthreads();
        for (int st = 512; st > 0; st >>= 1) {
            if (t < st) {
                float v2 = sv[t + st]; int i2 = si[t + st];
                if (v2 > sv[t] || (v2 == sv[t] && i2 < si[t])) { sv[t] = v2; si[t] = i2; }
            }
            __syncthreads();
        }
        if (t == 0) ssel[pass] = si[0];
        if (it == si[0]) vt = __int_as_float(0xff800000);
        __syncthreads();
    }
    float vb = g_cand_v[NB_TK * 8 + t];
    int ib = g_cand_i[NB_TK * 8 + t];
    for (int pass = 0; pass < 8; pass++) {
        sv[t] = vb; si[t] = ib; __syncthreads();
        for (int st = 512; st > 0; st >>= 1) {
            if (t < st) {
                float v2 = sv[t + st]; int i2 = si[t + st];
                if (v2 < sv[t] || (v2 == sv[t] && i2 < si[t])) { sv[t] = v2; si[t] = i2; }
            }
            __syncthreads();
        }
        if (t == 0) ssel[8 + pass] = si[0];
        if (ib == si[0]) vb = __int_as_float(0x7f800000);
        __syncthreads();
    }
    if (t != 0) return;
    g_done = 0u;  // reset for next graph replay
    float logits[NCLS];
#pragma unroll
    for (int c = 0; c < NCLS; c++) {
        float s = bcls[c];
#pragma unroll
        for (int f = 0; f < D1; f++) s += g_pooled[f] * Wcls[f * NCLS + c];
        logits[c] = s;
    }
    float mx = fmaxf(logits[0], fmaxf(logits[1], logits[2]));
    float e0 = expf(logits[0] - mx), e1 = expf(logits[1] - mx), e2 = expf(logits[2] - mx);
    float es = e0 + e1 + e2;
    int yhat = 0;
    if (logits[1] > logits[yhat]) yhat = 1;
    if (logits[2] > logits[yhat]) yhat = 2;
    out[0] = logits[0]; out[1] = logits[1]; out[2] = logits[2];
    out[3] = e0 / es; out[4] = e1 / es; out[5] = e2 / es;
    out[6] = (float)yhat;
    int label = labelp[0];
    if (label < 0) label = 0;
    if (label >= NCLS) label = NCLS - 1;
    const float* Wl = Wcell + label * D1 * 2;
    const float* bl = bcell + label * 2;
    float loss = 0.f;
    for (int i = 0; i < 16; i++) {
        int node = ssel[i];
        if (node < 0 || node >= NN) node = 0;
        int tgt = (i < 8) ? 1 : 0;
        const float* xr = g_x3 + (long)node * D1;
        float l0 = bl[0], l1 = bl[1];
#pragma unroll
        for (int f = 0; f < D1; f++) { l0 += xr[f] * Wl[f * 2]; l1 += xr[f] * Wl[f * 2 + 1]; }
        float u0 = l0 + (tgt == 1 ? 1.f : 0.f);
        float u1 = l1 + (tgt == 0 ? 1.f : 0.f);
        float mm = fmaxf(u0, u1);
        float lse = mm + logf(expf(u0 - mm) + expf(u1 - mm));
        float sy = tgt ? l1 : l0;
        loss += lse - sy;
    }
    out[OUT_LOSS] = loss * (1.f / 16.f);
}

// ---------------- launch ----------------
extern "C" void kernel_launch(void* const* d_in, const int* in_sizes, int n_in,
                              void* d_out, int out_size) {
    const float* x = (const float*)d_in[0];
    const void* ei = d_in[1];
    const float* ew = (const float*)d_in[2];
    const int* label = (const int*)d_in[3];
    const float* W1 = (const float*)d_in[4];
    const float* b1 = (const float*)d_in[5];
    const float* ln1w = (const float*)d_in[6];
    const float* ln1b = (const float*)d_in[7];
    const float* W2 = (const float*)d_in[8];
    const float* b2 = (const float*)d_in[9];
    const float* ln2w = (const float*)d_in[10];
    const float* ln2b = (const float*)d_in[11];
    const float* Wf = (const float*)d_in[12];
    const float* bf = (const float*)d_in[13];
    const float* Wt = (const float*)d_in[14];
    const float* bt = (const float*)d_in[15];
    const float* Ws = (const float*)d_in[16];
    const float* bs = (const float*)d_in[17];
    const float* Wc = (const float*)d_in[18];
    const float* bc = (const float*)d_in[19];
    const float* Wcls = (const float*)d_in[20];
    const float* bcls = (const float*)d_in[21];
    const float* Wcell = (const float*)d_in[22];
    const float* bcell = (const float*)d_in[23];
    float* out = (float*)d_out;

    int nb_scan = (NN + 1023) / 1024;        // 98
    int nb_node = (NN + 127) / 128;          // 782
    int nb_aggc = (NN + 7) / 8;              // 12500

    k_prepmm<<<NB_EDGE + NB_NODE, 256>>>(ei, ew, x, W1);
    k_scan1<<<nb_scan, 1024>>>();
    k_scan3<<<nb_scan, 1024>>>(nb_scan);
    k_scatter<<<NB_EDGE, 256>>>(ew);

    // layer 1
    k_aggc<<<nb_aggc, 256>>>(b1);
    k_post1mm<<<nb_node, 128>>>(ln1w, ln1b, W2);
    // layer 2
    k_aggc<<<nb_aggc, 256>>>(b2);
    k_post2<<<nb_node, 128>>>(ln2w, ln2b, Wf, bf, Wt, bt, Ws, bs, Wc, bc,
                              out + OUT_X3);

    // softmax + pool (fused finalize)
    k_softpool<<<NB_SP, 256>>>();

    // topk (+A write) and tail (+final)
    k_topk1<<<NB_TK, 1024>>>(out + OUT_A);
    k_topk2<<<1, 1024>>>(Wcls, bcls, Wcell, bcell, label, out);
}

// round 14
// speedup vs baseline: 1.0212x; 1.0212x over previous
#include <cuda_runtime.h>
#include <math.h>

#define NN 100000
#define NE 2000000
#define INC 30
#define HID 40
#define D1 20
#define D2 10
#define NCLS 3
#define NB_SP 128   // softpool blocks
#define NB_TK 128   // topk stage-1 blocks
#define NB_EDGE ((NE + 255) / 256)   // 7813
#define NB_NODE ((NN + 255) / 256)   // 391

// out layout: logits[3], Y_prob[3], Y_hat[1], A[NN], x3[NN*D1], cell_loss[1]
#define OUT_A 7
#define OUT_X3 (7 + NN)
#define OUT_LOSS (7 + NN + NN * D1)

// ---------------- scratch ----------------
__device__ __align__(16) float g_h[NN * HID];
__device__ __align__(16) float g_agg[NN * HID];
__device__ __align__(16) float g_x3[NN * D1];
__device__ float g_a[NN];
__device__ unsigned long long g_dc[NN];    // packed cnt<<40 | deg*2^28 (zero on entry; re-zeroed in scan3)
__device__ float g_dinv[NN];
__device__ int   g_pref[NN];
__device__ int   g_bsum[128];
__device__ int   g_rowstart[NN + 1];
__device__ unsigned long long g_sdr[NE];   // packed s | d<<17 | rank<<34
__device__ unsigned long long g_csr[NE];
__device__ float g_bm[NB_SP];
__device__ float g_bs[NB_SP];
__device__ float g_bp[NB_SP * D1];
__device__ float g_gmax;
__device__ float g_denom;
__device__ float g_pooled[D1];
__device__ float g_cand_v[2 * NB_TK * 8];
__device__ int   g_cand_i[2 * NB_TK * 8];
__device__ unsigned int g_done;            // zero on entry; re-zeroed in topk2

// ---------------- helpers ----------------
__device__ __forceinline__ float selu_f(float x) {
    const float sc = 1.0507009873554805f, al = 1.6732632423543772f;
    return x > 0.f ? sc * x : sc * al * expm1f(x);
}
__device__ __forceinline__ int clampn(int v) {
    return v < 0 ? 0 : (v >= NN ? NN - 1 : v);
}

// ---------------- kernels ----------------
// blocks [0, NB_EDGE): edge prep (single packed atomic, write (s,d,rank))
// blocks [NB_EDGE, NB_EDGE+NB_NODE): h = x @ W1
__global__ void k_prepmm(const void* __restrict__ eiv, const float* __restrict__ ew,
                         const float* __restrict__ X, const float* __restrict__ W) {
    if (blockIdx.x < NB_EDGE) {
        __shared__ int any_nz;
        const int* ei32 = (const int*)eiv;
        if (threadIdx.x == 0) any_nz = 0;
        __syncthreads();
        if (ei32[2 * threadIdx.x + 1] != 0) atomicOr(&any_nz, 1);
        __syncthreads();
        bool is64 = (any_nz == 0);
        int e = blockIdx.x * 256 + threadIdx.x;
        if (e >= NE) return;
        int s, d;
        if (is64) {
            const long long* ei = (const long long*)eiv;
            s = (int)ei[e]; d = (int)ei[NE + e];
        } else {
            s = ei32[e]; d = ei32[NE + e];
        }
        s = clampn(s); d = clampn(d);
        unsigned long long fx = (unsigned long long)(ew[e] * 268435456.0f + 0.5f);
        unsigned long long old = atomicAdd(&g_dc[d], (1ULL << 40) | fx);
        unsigned long long rank = old >> 40;
        g_sdr[e] = (unsigned long long)(unsigned)s |
                   ((unsigned long long)(unsigned)d << 17) | (rank << 34);
    } else {
        __shared__ float sW[INC * HID];
        for (int i = threadIdx.x; i < INC * HID; i += 256) sW[i] = W[i];
        __syncthreads();
        int n = (blockIdx.x - NB_EDGE) * 256 + threadIdx.x;
        if (n >= NN) return;
        float acc[HID];
#pragma unroll
        for (int o = 0; o < HID; o++) acc[o] = 0.f;
        const float* xr = X + (long)n * INC;
#pragma unroll
        for (int k = 0; k < INC; k++) {
            float xv = __ldg(xr + k);
#pragma unroll
            for (int o = 0; o < HID; o++) acc[o] += xv * sW[k * HID + o];
        }
        float* yr = g_h + (long)n * HID;
#pragma unroll
        for (int o = 0; o < HID; o++) yr[o] = acc[o];
    }
}

// block-local exclusive scan of counts
__global__ void k_scan1() {
    __shared__ int sm[1024];
    int t = threadIdx.x;
    int gid = blockIdx.x * 1024 + t;
    int x = (gid < NN) ? (int)(g_dc[gid] >> 40) : 0;
    sm[t] = x; __syncthreads();
    for (int off = 1; off < 1024; off <<= 1) {
        int v = (t >= off) ? sm[t - off] : 0;
        __syncthreads();
        sm[t] += v;
        __syncthreads();
    }
    if (gid < NN) g_pref[gid] = sm[t] - x;
    if (t == 1023) g_bsum[blockIdx.x] = sm[1023];
}

// add block offsets (serial 98-sum by t0) + rowstart/dinv; reset g_dc
__global__ void k_scan3(int nblk) {
    __shared__ int sb[128];
    __shared__ int soff;
    int t = threadIdx.x;
    if (t < 128) sb[t] = (t < nblk) ? g_bsum[t] : 0;
    __syncthreads();
    if (t == 0) {
        int s = 0;
        for (int j = 0; j < blockIdx.x; j++) s += sb[j];
        soff = s;
    }
    __syncthreads();
    int gid = blockIdx.x * 1024 + t;
    if (gid < NN) {
        g_rowstart[gid] = g_pref[gid] + soff;
        unsigned long long dc = g_dc[gid];
        float deg = (float)(dc & ((1ULL << 40) - 1ULL)) * (1.0f / 268435456.0f);
        g_dinv[gid] = rsqrtf(deg + 1.0f);
        g_dc[gid] = 0ULL;   // reset for next graph replay
    }
    if (gid == 0) g_rowstart[NN] = NE;
}

// build CSR entries (src, norm) — no atomics, position = rowstart[d] + rank
__global__ void k_scatter(const float* __restrict__ ew) {
    int e = blockIdx.x * 256 + threadIdx.x;
    if (e >= NE) return;
    unsigned long long ent = __ldg(&g_sdr[e]);
    int s = (int)(ent & 0x1FFFFULL);
    int d = (int)((ent >> 17) & 0x1FFFFULL);
    int rank = (int)(ent >> 34);
    float w = g_dinv[s] * __ldg(ew + e) * g_dinv[d];
    int pos = g_rowstart[d] + rank;
    g_csr[pos] = ((unsigned long long)__float_as_uint(w) << 32) | (unsigned int)s;
}

// CSR aggregation: warp per node, 30 lanes = 3 edges x 10 chunks.
// Unroll-2: 6 edges/iteration, two independent gathers in flight per lane,
// plus dual csr-entry prefetch. agg[n] = sum_e w_e*h[src_e] + h[n]*dinv^2 + b
__global__ void k_aggc(const float* __restrict__ b) {
    int warp = blockIdx.x * 8 + (threadIdx.x >> 5);
    if (warp >= NN) return;
    int lane = threadIdx.x & 31;
    int grp = lane / 10;          // 0..2 active, 3 idle (lanes 30,31)
    int chunk = lane - grp * 10;  // 0..9
    bool act = lane < 30;
    int beg = g_rowstart[warp], end = g_rowstart[warp + 1];
    const float4* h4 = reinterpret_cast<const float4*>(g_h);
    float4 acc = make_float4(0.f, 0.f, 0.f, 0.f);

    int e0 = beg + grp;
    unsigned long long ent0 = (act && e0 < end) ? __ldg(&g_csr[e0]) : 0ULL;
    unsigned long long ent1 = (act && e0 + 3 < end) ? __ldg(&g_csr[e0 + 3]) : 0ULL;
    for (int e = beg; e < end; e += 6) {
        bool v0ok = act && (e + grp) < end;
        bool v1ok = act && (e + 3 + grp) < end;
        unsigned long long cur0 = ent0;
        unsigned long long cur1 = ent1;
        int en0 = e + 6 + grp, en1 = e + 9 + grp;
        ent0 = (act && en0 < end) ? __ldg(&g_csr[en0]) : 0ULL;
        ent1 = (act && en1 < end) ? __ldg(&g_csr[en1]) : 0ULL;
        int s0 = (int)(unsigned int)cur0;
        int s1 = (int)(unsigned int)cur1;
        float w0 = v0ok ? __uint_as_float((unsigned int)(cur0 >> 32)) : 0.f;
        float w1 = v1ok ? __uint_as_float((unsigned int)(cur1 >> 32)) : 0.f;
        // both gathers issued back-to-back -> MLP=2 per lane
        float4 v0 = v0ok ? __ldg(h4 + s0 * 10 + chunk) : make_float4(0.f, 0.f, 0.f, 0.f);
        float4 v1 = v1ok ? __ldg(h4 + s1 * 10 + chunk) : make_float4(0.f, 0.f, 0.f, 0.f);
        acc.x += v0.x * w0 + v1.x * w1;
        acc.y += v0.y * w0 + v1.y * w1;
        acc.z += v0.z * w0 + v1.z * w1;
        acc.w += v0.w * w0 + v1.w * w1;
    }
    float rx = acc.x + __shfl_down_sync(0xffffffffu, acc.x, 10)
                     + __shfl_down_sync(0xffffffffu, acc.x, 20);
    float ry = acc.y + __shfl_down_sync(0xffffffffu, acc.y, 10)
                     + __shfl_down_sync(0xffffffffu, acc.y, 20);
    float rz = acc.z + __shfl_down_sync(0xffffffffu, acc.z, 10)
                     + __shfl_down_sync(0xffffffffu, acc.z, 20);
    float rw = acc.w + __shfl_down_sync(0xffffffffu, acc.w, 10)
                     + __shfl_down_sync(0xffffffffu, acc.w, 20);
    if (lane < 10) {
        float di = g_dinv[warp], d2 = di * di;
        float4 hv = h4[warp * 10 + lane];
        float4 bv = __ldg(reinterpret_cast<const float4*>(b) + lane);
        float4 r;
        r.x = rx + hv.x * d2 + bv.x;
        r.y = ry + hv.y * d2 + bv.y;
        r.z = rz + hv.z * d2 + bv.z;
        r.w = rw + hv.w * d2 + bv.w;
        reinterpret_cast<float4*>(g_agg)[warp * 10 + lane] = r;
    }
}

// x1 = selu(ln(agg)); h2 = x1 @ W2 -> g_h (overwrite)
__global__ void k_post1mm(const float* __restrict__ lw, const float* __restrict__ lb,
                          const float* __restrict__ W2) {
    __shared__ float sW[HID * HID];
    for (int i = threadIdx.x; i < HID * HID; i += blockDim.x) sW[i] = W2[i];
    __syncthreads();
    int n = blockIdx.x * blockDim.x + threadIdx.x;
    if (n >= NN) return;
    float v[HID];
    const float4* ag = reinterpret_cast<const float4*>(g_agg) + n * (HID / 4);
    float s = 0.f;
#pragma unroll
    for (int j = 0; j < HID / 4; j++) {
        float4 a4 = ag[j];
        v[4 * j + 0] = a4.x; v[4 * j + 1] = a4.y;
        v[4 * j + 2] = a4.z; v[4 * j + 3] = a4.w;
        s += a4.x + a4.y + a4.z + a4.w;
    }
    float m = s * (1.f / HID);
    float vs = 0.f;
#pragma unroll
    for (int f = 0; f < HID; f++) { float dd = v[f] - m; vs += dd * dd; }
    float inv = rsqrtf(vs * (1.f / HID) + 1e-5f);
#pragma unroll
    for (int f = 0; f < HID; f++)
        v[f] = selu_f((v[f] - m) * inv * __ldg(lw + f) + __ldg(lb + f));
    float acc[HID];
#pragma unroll
    for (int o = 0; o < HID; o++) acc[o] = 0.f;
#pragma unroll
    for (int k = 0; k < HID; k++) {
        float xv = v[k];
#pragma unroll
        for (int o = 0; o < HID; o++) acc[o] += xv * sW[k * HID + o];
    }
    float* yr = g_h + (long)n * HID;
#pragma unroll
    for (int o = 0; o < HID; o++) yr[o] = acc[o];
}

// x2 = selu(ln(agg)); x3 = selu(x2@Wf+bf) -> g_x3 + outx3; a = attention score
__global__ void k_post2(const float* __restrict__ lw, const float* __restrict__ lb,
                        const float* __restrict__ Wf, const float* __restrict__ bf,
                        const float* __restrict__ Wt, const float* __restrict__ bt,
                        const float* __restrict__ Ws, const float* __restrict__ bs,
                        const float* __restrict__ Wc, const float* __restrict__ bc,
                        float* __restrict__ outx3) {
    __shared__ float sWf[HID * D1];
    __shared__ float sWt[D1 * D2];
    __shared__ float sWs[D1 * D2];
    __shared__ float sWc[D2];
    __shared__ float sbf[D1], sbt[D2], sbs[D2];
    int t = threadIdx.x;
    for (int i = t; i < HID * D1; i += blockDim.x) sWf[i] = Wf[i];
    for (int i = t; i < D1 * D2; i += blockDim.x) { sWt[i] = Wt[i]; sWs[i] = Ws[i]; }
    if (t < D2) { sWc[t] = Wc[t]; sbt[t] = bt[t]; sbs[t] = bs[t]; }
    if (t < D1) sbf[t] = bf[t];
    __syncthreads();
    int n = blockIdx.x * blockDim.x + t;
    if (n >= NN) return;
    float v[HID];
    const float4* ag = reinterpret_cast<const float4*>(g_agg) + n * (HID / 4);
    float s = 0.f;
#pragma unroll
    for (int j = 0; j < HID / 4; j++) {
        float4 a4 = ag[j];
        v[4 * j + 0] = a4.x; v[4 * j + 1] = a4.y;
        v[4 * j + 2] = a4.z; v[4 * j + 3] = a4.w;
        s += a4.x + a4.y + a4.z + a4.w;
    }
    float m = s * (1.f / HID);
    float vs = 0.f;
#pragma unroll
    for (int f = 0; f < HID; f++) { float dd = v[f] - m; vs += dd * dd; }
    float inv = rsqrtf(vs * (1.f / HID) + 1e-5f);
#pragma unroll
    for (int f = 0; f < HID; f++)
        v[f] = selu_f((v[f] - m) * inv * __ldg(lw + f) + __ldg(lb + f));
    float x3[D1];
#pragma unroll
    for (int o = 0; o < D1; o++) {
        float acc = sbf[o];
#pragma unroll
        for (int k = 0; k < HID; k++) acc += v[k] * sWf[k * D1 + o];
        x3[o] = selu_f(acc);
    }
    float* xo = g_x3 + (long)n * D1;
    float* xo2 = outx3 + (long)n * D1;
#pragma unroll
    for (int o = 0; o < D1; o++) { xo[o] = x3[o]; xo2[o] = x3[o]; }
    float a = __ldg(bc);
#pragma unroll
    for (int j = 0; j < D2; j++) {
        float zt = sbt[j], zs = sbs[j];
#pragma unroll
        for (int k = 0; k < D1; k++) { zt += x3[k] * sWt[k * D2 + j]; zs += x3[k] * sWs[k * D2 + j]; }
        a += tanhf(zt) * (1.f / (1.f + expf(-zs))) * sWc[j];
    }
    g_a[n] = a;
}

// per-block (m, s, p) partials; last block finalizes gmax/denom/pooled
__global__ void k_softpool() {
    __shared__ float sm[256];
    __shared__ float sbp[D1];
    __shared__ bool isLast;
    int t = threadIdx.x;
    float mx = __int_as_float(0xff800000);
    for (int i = blockIdx.x * 256 + t; i < NN; i += NB_SP * 256)
        mx = fmaxf(mx, g_a[i]);
    sm[t] = mx; __syncthreads();
    for (int st = 128; st > 0; st >>= 1) {
        if (t < st) sm[t] = fmaxf(sm[t], sm[t + st]);
        __syncthreads();
    }
    float mb = sm[0];
    __syncthreads();
    float ssum = 0.f;
    float acc[D1];
#pragma unroll
    for (int f = 0; f < D1; f++) acc[f] = 0.f;
    for (int i = blockIdx.x * 256 + t; i < NN; i += NB_SP * 256) {
        float w = expf(g_a[i] - mb);
        ssum += w;
        const float4* xr = reinterpret_cast<const float4*>(g_x3) + i * (D1 / 4);
#pragma unroll
        for (int j = 0; j < D1 / 4; j++) {
            float4 t4 = __ldg(xr + j);
            acc[4 * j + 0] += w * t4.x; acc[4 * j + 1] += w * t4.y;
            acc[4 * j + 2] += w * t4.z; acc[4 * j + 3] += w * t4.w;
        }
    }
    sm[t] = ssum; __syncthreads();
    for (int st = 128; st > 0; st >>= 1) {
        if (t < st) sm[t] += sm[t + st];
        __syncthreads();
    }
    if (t == 0) { g_bm[blockIdx.x] = mb; g_bs[blockIdx.x] = sm[0]; }
    if (t < D1) sbp[t] = 0.f;
    __syncthreads();
#pragma unroll
    for (int f = 0; f < D1; f++) {
        float vv = acc[f];
        for (int off = 16; off; off >>= 1) vv += __shfl_down_sync(0xffffffffu, vv, off);
        if ((t & 31) == 0) atomicAdd(&sbp[f], vv);
    }
    __syncthreads();
    if (t < D1) g_bp[blockIdx.x * D1 + t] = sbp[t];
    __threadfence();
    if (t == 0) {
        unsigned int prev = atomicAdd(&g_done, 1u);
        isLast = (prev == NB_SP - 1);
    }
    __syncthreads();
    if (!isLast) return;
    __threadfence();
    float mt = (t < NB_SP) ? g_bm[t] : __int_as_float(0xff800000);
    sm[t] = mt; __syncthreads();
    for (int st = 128; st > 0; st >>= 1) {
        if (t < st) sm[t] = fmaxf(sm[t], sm[t + st]);
        __syncthreads();
    }
    float M = sm[0];
    __syncthreads();
    float scale = (t < NB_SP) ? expf(mt - M) : 0.f;
    sm[t] = (t < NB_SP) ? g_bs[t] * scale : 0.f;
    __syncthreads();
    for (int st = 128; st > 0; st >>= 1) {
        if (t < st) sm[t] += sm[t + st];
        __syncthreads();
    }
    float denom = sm[0];
    if (t == 0) { g_gmax = M; g_denom = denom; }
    __syncthreads();
    for (int f = 0; f < D1; f++) {
        sm[t] = (t < NB_SP) ? g_bp[t * D1 + f] * scale : 0.f;
        __syncthreads();
        for (int st = 128; st > 0; st >>= 1) {
            if (t < st) sm[t] += sm[t + st];
            __syncthreads();
        }
        if (t == 0) g_pooled[f] = sm[0] / denom;
        __syncthreads();
    }
}

// stage-1 topk: each block = 1024 contiguous elements; also writes softmax A
__global__ void k_topk1(float* __restrict__ outA) {
    __shared__ float sv[1024];
    __shared__ int si[1024];
    int t = threadIdx.x;
    int gid = blockIdx.x * 1024 + t;
    bool valid = gid < NN;
    float a = valid ? g_a[gid] : 0.f;
    if (valid) outA[gid] = expf(a - g_gmax) / g_denom;
    float vt = valid ? a : __int_as_float(0xff800000);
    float vb = valid ? a : __int_as_float(0x7f800000);
    int myi = valid ? gid : 0x7fffffff;
    for (int pass = 0; pass < 8; pass++) {
        sv[t] = vt; si[t] = myi; __syncthreads();
        for (int st = 512; st > 0; st >>= 1) {
            if (t < st) {
                float v2 = sv[t + st]; int i2 = si[t + st];
                if (v2 > sv[t] || (v2 == sv[t] && i2 < si[t])) { sv[t] = v2; si[t] = i2; }
            }
            __syncthreads();
        }
        if (t == 0) {
            g_cand_v[blockIdx.x * 8 + pass] = sv[0];
            g_cand_i[blockIdx.x * 8 + pass] = si[0];
        }
        if (myi == si[0]) vt = __int_as_float(0xff800000);
        __syncthreads();
    }
    for (int pass = 0; pass < 8; pass++) {
        sv[t] = vb; si[t] = myi; __syncthreads();
        for (int st = 512; st > 0; st >>= 1) {
            if (t < st) {
                float v2 = sv[t + st]; int i2 = si[t + st];
                if (v2 < sv[t] || (v2 == sv[t] && i2 < si[t])) { sv[t] = v2; si[t] = i2; }
            }
            __syncthreads();
        }
        if (t == 0) {
            g_cand_v[NB_TK * 8 + blockIdx.x * 8 + pass] = sv[0];
            g_cand_i[NB_TK * 8 + blockIdx.x * 8 + pass] = si[0];
        }
        if (myi == si[0]) vb = __int_as_float(0x7f800000);
        __syncthreads();
    }
}

// stage-2 merge + final tail math; resets g_done for next replay
__global__ void k_topk2(const float* __restrict__ Wcls, const float* __restrict__ bcls,
                        const float* __restrict__ Wcell, const float* __restrict__ bcell,
                        const int* __restrict__ labelp, float* __restrict__ out) {
    __shared__ float sv[1024];
    __shared__ int si[1024];
    __shared__ int ssel[16];
    int t = threadIdx.x;
    float vt = g_cand_v[t];
    int it = g_cand_i[t];
    for (int pass = 0; pass < 8; pass++) {
        sv[t] = vt; si[t] = it; __syncthreads();
        for (int st = 512; st > 0; st >>= 1) {
            if (t < st) {
                float v2 = sv[t + st]; int i2 = si[t + st];
                if (v2 > sv[t] || (v2 == sv[t] && i2 < si[t])) { sv[t] = v2; si[t] = i2; }
            }
            __syncthreads();
        }
        if (t == 0) ssel[pass] = si[0];
        if (it == si[0]) vt = __int_as_float(0xff800000);
        __syncthreads();
    }
    float vb = g_cand_v[NB_TK * 8 + t];
    int ib = g_cand_i[NB_TK * 8 + t];
    for (int pass = 0; pass < 8; pass++) {
        sv[t] = vb; si[t] = ib; __syncthreads();
        for (int st = 512; st > 0; st >>= 1) {
            if (t < st) {
                float v2 = sv[t + st]; int i2 = si[t + st];
                if (v2 < sv[t] || (v2 == sv[t] && i2 < si[t])) { sv[t] = v2; si[t] = i2; }
            }
            __syncthreads();
        }
        if (t == 0) ssel[8 + pass] = si[0];
        if (ib == si[0]) vb = __int_as_float(0x7f800000);
        __syncthreads();
    }
    if (t != 0) return;
    g_done = 0u;  // reset for next graph replay
    float logits[NCLS];
#pragma unroll
    for (int c = 0; c < NCLS; c++) {
        float s = bcls[c];
#pragma unroll
        for (int f = 0; f < D1; f++) s += g_pooled[f] * Wcls[f * NCLS + c];
        logits[c] = s;
    }
    float mx = fmaxf(logits[0], fmaxf(logits[1], logits[2]));
    float e0 = expf(logits[0] - mx), e1 = expf(logits[1] - mx), e2 = expf(logits[2] - mx);
    float es = e0 + e1 + e2;
    int yhat = 0;
    if (logits[1] > logits[yhat]) yhat = 1;
    if (logits[2] > logits[yhat]) yhat = 2;
    out[0] = logits[0]; out[1] = logits[1]; out[2] = logits[2];
    out[3] = e0 / es; out[4] = e1 / es; out[5] = e2 / es;
    out[6] = (float)yhat;
    int label = labelp[0];
    if (label < 0) label = 0;
    if (label >= NCLS) label = NCLS - 1;
    const float* Wl = Wcell + label * D1 * 2;
    const float* bl = bcell + label * 2;
    float loss = 0.f;
    for (int i = 0; i < 16; i++) {
        int node = ssel[i];
        if (node < 0 || node >= NN) node = 0;
        int tgt = (i < 8) ? 1 : 0;
        const float* xr = g_x3 + (long)node * D1;
        float l0 = bl[0], l1 = bl[1];
#pragma unroll
        for (int f = 0; f < D1; f++) { l0 += xr[f] * Wl[f * 2]; l1 += xr[f] * Wl[f * 2 + 1]; }
        float u0 = l0 + (tgt == 1 ? 1.f : 0.f);
        float u1 = l1 + (tgt == 0 ? 1.f : 0.f);
        float mm = fmaxf(u0, u1);
        float lse = mm + logf(expf(u0 - mm) + expf(u1 - mm));
        float sy = tgt ? l1 : l0;
        loss += lse - sy;
    }
    out[OUT_LOSS] = loss * (1.f / 16.f);
}

// ---------------- launch ----------------
extern "C" void kernel_launch(void* const* d_in, const int* in_sizes, int n_in,
                              void* d_out, int out_size) {
    const float* x = (const float*)d_in[0];
    const void* ei = d_in[1];
    const float* ew = (const float*)d_in[2];
    const int* label = (const int*)d_in[3];
    const float* W1 = (const float*)d_in[4];
    const float* b1 = (const float*)d_in[5];
    const float* ln1w = (const float*)d_in[6];
    const float* ln1b = (const float*)d_in[7];
    const float* W2 = (const float*)d_in[8];
    const float* b2 = (const float*)d_in[9];
    const float* ln2w = (const float*)d_in[10];
    const float* ln2b = (const float*)d_in[11];
    const float* Wf = (const float*)d_in[12];
    const float* bf = (const float*)d_in[13];
    const float* Wt = (const float*)d_in[14];
    const float* bt = (const float*)d_in[15];
    const float* Ws = (const float*)d_in[16];
    const float* bs = (const float*)d_in[17];
    const float* Wc = (const float*)d_in[18];
    const float* bc = (const float*)d_in[19];
    const float* Wcls = (const float*)d_in[20];
    const float* bcls = (const float*)d_in[21];
    const float* Wcell = (const float*)d_in[22];
    const float* bcell = (const float*)d_in[23];
    float* out = (float*)d_out;

    int nb_scan = (NN + 1023) / 1024;        // 98
    int nb_node = (NN + 127) / 128;          // 782
    int nb_aggc = (NN + 7) / 8;              // 12500

    k_prepmm<<<NB_EDGE + NB_NODE, 256>>>(ei, ew, x, W1);
    k_scan1<<<nb_scan, 1024>>>();
    k_scan3<<<nb_scan, 1024>>>(nb_scan);
    k_scatter<<<NB_EDGE, 256>>>(ew);

    // layer 1
    k_aggc<<<nb_aggc, 256>>>(b1);
    k_post1mm<<<nb_node, 128>>>(ln1w, ln1b, W2);
    // layer 2
    k_aggc<<<nb_aggc, 256>>>(b2);
    k_post2<<<nb_node, 128>>>(ln2w, ln2b, Wf, bf, Wt, bt, Ws, bs, Wc, bc,
                              out + OUT_X3);

    // softmax + pool (fused finalize)
    k_softpool<<<NB_SP, 256>>>();

    // topk (+A write) and tail (+final)
    k_topk1<<<NB_TK, 1024>>>(out + OUT_A);
    k_topk2<<<1, 1024>>>(Wcls, bcls, Wcell, bcell, label, out);
}

// round 15
// speedup vs baseline: 1.0366x; 1.0152x over previous
#include <cuda_runtime.h>
#include <math.h>

#define NN 100000
#define NE 2000000
#define INC 30
#define HID 40
#define D1 20
#define D2 10
#define NCLS 3
#define NB_SP 128   // softpool blocks
#define NB_TK 128   // topk stage-1 blocks
#define NB_EDGE ((NE + 255) / 256)   // 7813
#define NB_NODE ((NN + 255) / 256)   // 391

// out layout: logits[3], Y_prob[3], Y_hat[1], A[NN], x3[NN*D1], cell_loss[1]
#define OUT_A 7
#define OUT_X3 (7 + NN)
#define OUT_LOSS (7 + NN + NN * D1)

// ---------------- scratch ----------------
__device__ __align__(16) float g_h[NN * HID];
__device__ __align__(16) float g_agg[NN * HID];
__device__ __align__(16) float g_x3[NN * D1];
__device__ float g_a[NN];
__device__ unsigned long long g_dc[NN];    // packed cnt<<40 | deg*2^28 (zero on entry; re-zeroed in scan3)
__device__ float g_dinv[NN];
__device__ int   g_pref[NN];
__device__ int   g_bsum[128];
__device__ int   g_rowstart[NN + 1];
__device__ unsigned long long g_sdr[NE];   // packed s | d<<17 | rank<<34
__device__ unsigned long long g_csr[NE];
__device__ float g_bm[NB_SP];
__device__ float g_bs[NB_SP];
__device__ float g_bp[NB_SP * D1];
__device__ float g_gmax;
__device__ float g_denom;
__device__ float g_pooled[D1];
__device__ float g_cand_v[2 * NB_TK * 8];
__device__ int   g_cand_i[2 * NB_TK * 8];
__device__ unsigned int g_done;            // zero on entry; re-zeroed in topk2

// ---------------- helpers ----------------
__device__ __forceinline__ float selu_f(float x) {
    const float sc = 1.0507009873554805f, al = 1.6732632423543772f;
    return x > 0.f ? sc * x : sc * al * expm1f(x);
}
__device__ __forceinline__ int clampn(int v) {
    return v < 0 ? 0 : (v >= NN ? NN - 1 : v);
}

// ---------------- kernels ----------------
// blocks [0, NB_EDGE): edge prep (single packed atomic, write (s,d,rank))
// blocks [NB_EDGE, NB_EDGE+NB_NODE): h = x @ W1
__global__ void k_prepmm(const void* __restrict__ eiv, const float* __restrict__ ew,
                         const float* __restrict__ X, const float* __restrict__ W) {
    if (blockIdx.x < NB_EDGE) {
        __shared__ int any_nz;
        const int* ei32 = (const int*)eiv;
        if (threadIdx.x == 0) any_nz = 0;
        __syncthreads();
        if (ei32[2 * threadIdx.x + 1] != 0) atomicOr(&any_nz, 1);
        __syncthreads();
        bool is64 = (any_nz == 0);
        int e = blockIdx.x * 256 + threadIdx.x;
        if (e >= NE) return;
        int s, d;
        if (is64) {
            const long long* ei = (const long long*)eiv;
            s = (int)ei[e]; d = (int)ei[NE + e];
        } else {
            s = ei32[e]; d = ei32[NE + e];
        }
        s = clampn(s); d = clampn(d);
        unsigned long long fx = (unsigned long long)(ew[e] * 268435456.0f + 0.5f);
        unsigned long long old = atomicAdd(&g_dc[d], (1ULL << 40) | fx);
        unsigned long long rank = old >> 40;
        g_sdr[e] = (unsigned long long)(unsigned)s |
                   ((unsigned long long)(unsigned)d << 17) | (rank << 34);
    } else {
        __shared__ float sW[INC * HID];
        for (int i = threadIdx.x; i < INC * HID; i += 256) sW[i] = W[i];
        __syncthreads();
        int n = (blockIdx.x - NB_EDGE) * 256 + threadIdx.x;
        if (n >= NN) return;
        float acc[HID];
#pragma unroll
        for (int o = 0; o < HID; o++) acc[o] = 0.f;
        const float* xr = X + (long)n * INC;
#pragma unroll
        for (int k = 0; k < INC; k++) {
            float xv = __ldg(xr + k);
#pragma unroll
            for (int o = 0; o < HID; o++) acc[o] += xv * sW[k * HID + o];
        }
        float* yr = g_h + (long)n * HID;
#pragma unroll
        for (int o = 0; o < HID; o++) yr[o] = acc[o];
    }
}

// block-local exclusive scan of counts
__global__ void k_scan1() {
    __shared__ int sm[1024];
    int t = threadIdx.x;
    int gid = blockIdx.x * 1024 + t;
    int x = (gid < NN) ? (int)(g_dc[gid] >> 40) : 0;
    sm[t] = x; __syncthreads();
    for (int off = 1; off < 1024; off <<= 1) {
        int v = (t >= off) ? sm[t - off] : 0;
        __syncthreads();
        sm[t] += v;
        __syncthreads();
    }
    if (gid < NN) g_pref[gid] = sm[t] - x;
    if (t == 1023) g_bsum[blockIdx.x] = sm[1023];
}

// add block offsets (serial 98-sum by t0) + rowstart/dinv; reset g_dc
__global__ void k_scan3(int nblk) {
    __shared__ int sb[128];
    __shared__ int soff;
    int t = threadIdx.x;
    if (t < 128) sb[t] = (t < nblk) ? g_bsum[t] : 0;
    __syncthreads();
    if (t == 0) {
        int s = 0;
        for (int j = 0; j < blockIdx.x; j++) s += sb[j];
        soff = s;
    }
    __syncthreads();
    int gid = blockIdx.x * 1024 + t;
    if (gid < NN) {
        g_rowstart[gid] = g_pref[gid] + soff;
        unsigned long long dc = g_dc[gid];
        float deg = (float)(dc & ((1ULL << 40) - 1ULL)) * (1.0f / 268435456.0f);
        g_dinv[gid] = rsqrtf(deg + 1.0f);
        g_dc[gid] = 0ULL;   // reset for next graph replay
    }
    if (gid == 0) g_rowstart[NN] = NE;
}

// build CSR entries (src, dinv[s]*ew) — dinv[d] is folded into k_aggc's final
// scaling, halving the random dinv gathers here. No atomics.
__global__ void k_scatter(const float* __restrict__ ew) {
    int e = blockIdx.x * 256 + threadIdx.x;
    if (e >= NE) return;
    unsigned long long ent = __ldg(&g_sdr[e]);
    int s = (int)(ent & 0x1FFFFULL);
    int d = (int)((ent >> 17) & 0x1FFFFULL);
    int rank = (int)(ent >> 34);
    float w = g_dinv[s] * __ldg(ew + e);
    int pos = g_rowstart[d] + rank;
    g_csr[pos] = ((unsigned long long)__float_as_uint(w) << 32) | (unsigned int)s;
}

// CSR aggregation: warp per node, 30 lanes = 3 edges x 10 chunks.
// Unroll-2 (MLP=2) + dual csr prefetch. Row sum is scaled by dinv[d] at end:
// agg[n] = dinv[n] * sum_e (dinv[s]*ew_e) h[src_e] + h[n]*dinv[n]^2 + b
__global__ void k_aggc(const float* __restrict__ b) {
    int warp = blockIdx.x * 8 + (threadIdx.x >> 5);
    if (warp >= NN) return;
    int lane = threadIdx.x & 31;
    int grp = lane / 10;          // 0..2 active, 3 idle (lanes 30,31)
    int chunk = lane - grp * 10;  // 0..9
    bool act = lane < 30;
    int beg = g_rowstart[warp], end = g_rowstart[warp + 1];
    const float4* h4 = reinterpret_cast<const float4*>(g_h);
    float4 acc = make_float4(0.f, 0.f, 0.f, 0.f);

    int e0 = beg + grp;
    unsigned long long ent0 = (act && e0 < end) ? __ldg(&g_csr[e0]) : 0ULL;
    unsigned long long ent1 = (act && e0 + 3 < end) ? __ldg(&g_csr[e0 + 3]) : 0ULL;
    for (int e = beg; e < end; e += 6) {
        bool v0ok = act && (e + grp) < end;
        bool v1ok = act && (e + 3 + grp) < end;
        unsigned long long cur0 = ent0;
        unsigned long long cur1 = ent1;
        int en0 = e + 6 + grp, en1 = e + 9 + grp;
        ent0 = (act && en0 < end) ? __ldg(&g_csr[en0]) : 0ULL;
        ent1 = (act && en1 < end) ? __ldg(&g_csr[en1]) : 0ULL;
        int s0 = (int)(unsigned int)cur0;
        int s1 = (int)(unsigned int)cur1;
        float w0 = v0ok ? __uint_as_float((unsigned int)(cur0 >> 32)) : 0.f;
        float w1 = v1ok ? __uint_as_float((unsigned int)(cur1 >> 32)) : 0.f;
        float4 v0 = v0ok ? __ldg(h4 + s0 * 10 + chunk) : make_float4(0.f, 0.f, 0.f, 0.f);
        float4 v1 = v1ok ? __ldg(h4 + s1 * 10 + chunk) : make_float4(0.f, 0.f, 0.f, 0.f);
        acc.x += v0.x * w0 + v1.x * w1;
        acc.y += v0.y * w0 + v1.y * w1;
        acc.z += v0.z * w0 + v1.z * w1;
        acc.w += v0.w * w0 + v1.w * w1;
    }
    float rx = acc.x + __shfl_down_sync(0xffffffffu, acc.x, 10)
                     + __shfl_down_sync(0xffffffffu, acc.x, 20);
    float ry = acc.y + __shfl_down_sync(0xffffffffu, acc.y, 10)
                     + __shfl_down_sync(0xffffffffu, acc.y, 20);
    float rz = acc.z + __shfl_down_sync(0xffffffffu, acc.z, 10)
                     + __shfl_down_sync(0xffffffffu, acc.z, 20);
    float rw = acc.w + __shfl_down_sync(0xffffffffu, acc.w, 10)
                     + __shfl_down_sync(0xffffffffu, acc.w, 20);
    if (lane < 10) {
        float di = g_dinv[warp], d2 = di * di;
        float4 hv = h4[warp * 10 + lane];
        float4 bv = __ldg(reinterpret_cast<const float4*>(b) + lane);
        float4 r;
        r.x = rx * di + hv.x * d2 + bv.x;
        r.y = ry * di + hv.y * d2 + bv.y;
        r.z = rz * di + hv.z * d2 + bv.z;
        r.w = rw * di + hv.w * d2 + bv.w;
        reinterpret_cast<float4*>(g_agg)[warp * 10 + lane] = r;
    }
}

// x1 = selu(ln(agg)); h2 = x1 @ W2 -> g_h (overwrite)
__global__ void k_post1mm(const float* __restrict__ lw, const float* __restrict__ lb,
                          const float* __restrict__ W2) {
    __shared__ float sW[HID * HID];
    for (int i = threadIdx.x; i < HID * HID; i += blockDim.x) sW[i] = W2[i];
    __syncthreads();
    int n = blockIdx.x * blockDim.x + threadIdx.x;
    if (n >= NN) return;
    float v[HID];
    const float4* ag = reinterpret_cast<const float4*>(g_agg) + n * (HID / 4);
    float s = 0.f;
#pragma unroll
    for (int j = 0; j < HID / 4; j++) {
        float4 a4 = ag[j];
        v[4 * j + 0] = a4.x; v[4 * j + 1] = a4.y;
        v[4 * j + 2] = a4.z; v[4 * j + 3] = a4.w;
        s += a4.x + a4.y + a4.z + a4.w;
    }
    float m = s * (1.f / HID);
    float vs = 0.f;
#pragma unroll
    for (int f = 0; f < HID; f++) { float dd = v[f] - m; vs += dd * dd; }
    float inv = rsqrtf(vs * (1.f / HID) + 1e-5f);
#pragma unroll
    for (int f = 0; f < HID; f++)
        v[f] = selu_f((v[f] - m) * inv * __ldg(lw + f) + __ldg(lb + f));
    float acc[HID];
#pragma unroll
    for (int o = 0; o < HID; o++) acc[o] = 0.f;
#pragma unroll
    for (int k = 0; k < HID; k++) {
        float xv = v[k];
#pragma unroll
        for (int o = 0; o < HID; o++) acc[o] += xv * sW[k * HID + o];
    }
    float* yr = g_h + (long)n * HID;
#pragma unroll
    for (int o = 0; o < HID; o++) yr[o] = acc[o];
}

// x2 = selu(ln(agg)); x3 = selu(x2@Wf+bf) -> g_x3 + outx3; a = attention score
__global__ void k_post2(const float* __restrict__ lw, const float* __restrict__ lb,
                        const float* __restrict__ Wf, const float* __restrict__ bf,
                        const float* __restrict__ Wt, const float* __restrict__ bt,
                        const float* __restrict__ Ws, const float* __restrict__ bs,
                        const float* __restrict__ Wc, const float* __restrict__ bc,
                        float* __restrict__ outx3) {
    __shared__ float sWf[HID * D1];
    __shared__ float sWt[D1 * D2];
    __shared__ float sWs[D1 * D2];
    __shared__ float sWc[D2];
    __shared__ float sbf[D1], sbt[D2], sbs[D2];
    int t = threadIdx.x;
    for (int i = t; i < HID * D1; i += blockDim.x) sWf[i] = Wf[i];
    for (int i = t; i < D1 * D2; i += blockDim.x) { sWt[i] = Wt[i]; sWs[i] = Ws[i]; }
    if (t < D2) { sWc[t] = Wc[t]; sbt[t] = bt[t]; sbs[t] = bs[t]; }
    if (t < D1) sbf[t] = bf[t];
    __syncthreads();
    int n = blockIdx.x * blockDim.x + t;
    if (n >= NN) return;
    float v[HID];
    const float4* ag = reinterpret_cast<const float4*>(g_agg) + n * (HID / 4);
    float s = 0.f;
#pragma unroll
    for (int j = 0; j < HID / 4; j++) {
        float4 a4 = ag[j];
        v[4 * j + 0] = a4.x; v[4 * j + 1] = a4.y;
        v[4 * j + 2] = a4.z; v[4 * j + 3] = a4.w;
        s += a4.x + a4.y + a4.z + a4.w;
    }
    float m = s * (1.f / HID);
    float vs = 0.f;
#pragma unroll
    for (int f = 0; f < HID; f++) { float dd = v[f] - m; vs += dd * dd; }
    float inv = rsqrtf(vs * (1.f / HID) + 1e-5f);
#pragma unroll
    for (int f = 0; f < HID; f++)
        v[f] = selu_f((v[f] - m) * inv * __ldg(lw + f) + __ldg(lb + f));
    float x3[D1];
#pragma unroll
    for (int o = 0; o < D1; o++) {
        float acc = sbf[o];
#pragma unroll
        for (int k = 0; k < HID; k++) acc += v[k] * sWf[k * D1 + o];
        x3[o] = selu_f(acc);
    }
    float* xo = g_x3 + (long)n * D1;
    float* xo2 = outx3 + (long)n * D1;
#pragma unroll
    for (int o = 0; o < D1; o++) { xo[o] = x3[o]; xo2[o] = x3[o]; }
    float a = __ldg(bc);
#pragma unroll
    for (int j = 0; j < D2; j++) {
        float zt = sbt[j], zs = sbs[j];
#pragma unroll
        for (int k = 0; k < D1; k++) { zt += x3[k] * sWt[k * D2 + j]; zs += x3[k] * sWs[k * D2 + j]; }
        a += tanhf(zt) * (1.f / (1.f + expf(-zs))) * sWc[j];
    }
    g_a[n] = a;
}

// per-block (m, s, p) partials; last block finalizes gmax/denom/pooled
__global__ void k_softpool() {
    __shared__ float sm[256];
    __shared__ float sbp[D1];
    __shared__ bool isLast;
    int t = threadIdx.x;
    float mx = __int_as_float(0xff800000);
    for (int i = blockIdx.x * 256 + t; i < NN; i += NB_SP * 256)
        mx = fmaxf(mx, g_a[i]);
    sm[t] = mx; __syncthreads();
    for (int st = 128; st > 0; st >>= 1) {
        if (t < st) sm[t] = fmaxf(sm[t], sm[t + st]);
        __syncthreads();
    }
    float mb = sm[0];
    __syncthreads();
    float ssum = 0.f;
    float acc[D1];
#pragma unroll
    for (int f = 0; f < D1; f++) acc[f] = 0.f;
    for (int i = blockIdx.x * 256 + t; i < NN; i += NB_SP * 256) {
        float w = expf(g_a[i] - mb);
        ssum += w;
        const float4* xr = reinterpret_cast<const float4*>(g_x3) + i * (D1 / 4);
#pragma unroll
        for (int j = 0; j < D1 / 4; j++) {
            float4 t4 = __ldg(xr + j);
            acc[4 * j + 0] += w * t4.x; acc[4 * j + 1] += w * t4.y;
            acc[4 * j + 2] += w * t4.z; acc[4 * j + 3] += w * t4.w;
        }
    }
    sm[t] = ssum; __syncthreads();
    for (int st = 128; st > 0; st >>= 1) {
        if (t < st) sm[t] += sm[t + st];
        __syncthreads();
    }
    if (t == 0) { g_bm[blockIdx.x] = mb; g_bs[blockIdx.x] = sm[0]; }
    if (t < D1) sbp[t] = 0.f;
    __syncthreads();
#pragma unroll
    for (int f = 0; f < D1; f++) {
        float vv = acc[f];
        for (int off = 16; off; off >>= 1) vv += __shfl_down_sync(0xffffffffu, vv, off);
        if ((t & 31) == 0) atomicAdd(&sbp[f], vv);
    }
    __syncthreads();
    if (t < D1) g_bp[blockIdx.x * D1 + t] = sbp[t];
    __threadfence();
    if (t == 0) {
        unsigned int prev = atomicAdd(&g_done, 1u);
        isLast = (prev == NB_SP - 1);
    }
    __syncthreads();
    if (!isLast) return;
    __threadfence();
    float mt = (t < NB_SP) ? g_bm[t] : __int_as_float(0xff800000);
    sm[t] = mt; __syncthreads();
    for (int st = 128; st > 0; st >>= 1) {
        if (t < st) sm[t] = fmaxf(sm[t], sm[t + st]);
        __syncthreads();
    }
    float M = sm[0];
    __syncthreads();
    float scale = (t < NB_SP) ? expf(mt - M) : 0.f;
    sm[t] = (t < NB_SP) ? g_bs[t] * scale : 0.f;
    __syncthreads();
    for (int st = 128; st > 0; st >>= 1) {
        if (t < st) sm[t] += sm[t + st];
        __syncthreads();
    }
    float denom = sm[0];
    if (t == 0) { g_gmax = M; g_denom = denom; }
    __syncthreads();
    for (int f = 0; f < D1; f++) {
        sm[t] = (t < NB_SP) ? g_bp[t * D1 + f] * scale : 0.f;
        __syncthreads();
        for (int st = 128; st > 0; st >>= 1) {
            if (t < st) sm[t] += sm[t + st];
            __syncthreads();
        }
        if (t == 0) g_pooled[f] = sm[0] / denom;
        __syncthreads();
    }
}

// stage-1 topk: each block = 1024 contiguous elements; also writes softmax A
__global__ void k_topk1(float* __restrict__ outA) {
    __shared__ float sv[1024];
    __shared__ int si[1024];
    int t = threadIdx.x;
    int gid = blockIdx.x * 1024 + t;
    bool valid = gid < NN;
    float a = valid ? g_a[gid] : 0.f;
    if (valid) outA[gid] = expf(a - g_gmax) / g_denom;
    float vt = valid ? a : __int_as_float(0xff800000);
    float vb = valid ? a : __int_as_float(0x7f800000);
    int myi = valid ? gid : 0x7fffffff;
    for (int pass = 0; pass < 8; pass++) {
        sv[t] = vt; si[t] = myi; __syncthreads();
        for (int st = 512; st > 0; st >>= 1) {
            if (t < st) {
                float v2 = sv[t + st]; int i2 = si[t + st];
                if (v2 > sv[t] || (v2 == sv[t] && i2 < si[t])) { sv[t] = v2; si[t] = i2; }
            }
            __syncthreads();
        }
        if (t == 0) {
            g_cand_v[blockIdx.x * 8 + pass] = sv[0];
            g_cand_i[blockIdx.x * 8 + pass] = si[0];
        }
        if (myi == si[0]) vt = __int_as_float(0xff800000);
        __syncthreads();
    }
    for (int pass = 0; pass < 8; pass++) {
        sv[t] = vb; si[t] = myi; __syncthreads();
        for (int st = 512; st > 0; st >>= 1) {
            if (t < st) {
                float v2 = sv[t + st]; int i2 = si[t + st];
                if (v2 < sv[t] || (v2 == sv[t] && i2 < si[t])) { sv[t] = v2; si[t] = i2; }
            }
            __syncthreads();
        }
        if (t == 0) {
            g_cand_v[NB_TK * 8 + blockIdx.x * 8 + pass] = sv[0];
            g_cand_i[NB_TK * 8 + blockIdx.x * 8 + pass] = si[0];
        }
        if (myi == si[0]) vb = __int_as_float(0x7f800000);
        __syncthreads();
    }
}

// stage-2 merge + final tail math; resets g_done for next replay
__global__ void k_topk2(const float* __restrict__ Wcls, const float* __restrict__ bcls,
                        const float* __restrict__ Wcell, const float* __restrict__ bcell,
                        const int* __restrict__ labelp, float* __restrict__ out) {
    __shared__ float sv[1024];
    __shared__ int si[1024];
    __shared__ int ssel[16];
    int t = threadIdx.x;
    float vt = g_cand_v[t];
    int it = g_cand_i[t];
    for (int pass = 0; pass < 8; pass++) {
        sv[t] = vt; si[t] = it; __syncthreads();
        for (int st = 512; st > 0; st >>= 1) {
            if (t < st) {
                float v2 = sv[t + st]; int i2 = si[t + st];
                if (v2 > sv[t] || (v2 == sv[t] && i2 < si[t])) { sv[t] = v2; si[t] = i2; }
            }
            __syncthreads();
        }
        if (t == 0) ssel[pass] = si[0];
        if (it == si[0]) vt = __int_as_float(0xff800000);
        __syncthreads();
    }
    float vb = g_cand_v[NB_TK * 8 + t];
    int ib = g_cand_i[NB_TK * 8 + t];
    for (int pass = 0; pass < 8; pass++) {
        sv[t] = vb; si[t] = ib; __syncthreads();
        for (int st = 512; st > 0; st >>= 1) {
            if (t < st) {
                float v2 = sv[t + st]; int i2 = si[t + st];
                if (v2 < sv[t] || (v2 == sv[t] && i2 < si[t])) { sv[t] = v2; si[t] = i2; }
            }
            __syncthreads();
        }
        if (t == 0) ssel[8 + pass] = si[0];
        if (ib == si[0]) vb = __int_as_float(0x7f800000);
        __syncthreads();
    }
    if (t != 0) return;
    g_done = 0u;  // reset for next graph replay
    float logits[NCLS];
#pragma unroll
    for (int c = 0; c < NCLS; c++) {
        float s = bcls[c];
#pragma unroll
        for (int f = 0; f < D1; f++) s += g_pooled[f] * Wcls[f * NCLS + c];
        logits[c] = s;
    }
    float mx = fmaxf(logits[0], fmaxf(logits[1], logits[2]));
    float e0 = expf(logits[0] - mx), e1 = expf(logits[1] - mx), e2 = expf(logits[2] - mx);
    float es = e0 + e1 + e2;
    int yhat = 0;
    if (logits[1] > logits[yhat]) yhat = 1;
    if (logits[2] > logits[yhat]) yhat = 2;
    out[0] = logits[0]; out[1] = logits[1]; out[2] = logits[2];
    out[3] = e0 / es; out[4] = e1 / es; out[5] = e2 / es;
    out[6] = (float)yhat;
    int label = labelp[0];
    if (label < 0) label = 0;
    if (label >= NCLS) label = NCLS - 1;
    const float* Wl = Wcell + label * D1 * 2;
    const float* bl = bcell + label * 2;
    float loss = 0.f;
    for (int i = 0; i < 16; i++) {
        int node = ssel[i];
        if (node < 0 || node >= NN) node = 0;
        int tgt = (i < 8) ? 1 : 0;
        const float* xr = g_x3 + (long)node * D1;
        float l0 = bl[0], l1 = bl[1];
#pragma unroll
        for (int f = 0; f < D1; f++) { l0 += xr[f] * Wl[f * 2]; l1 += xr[f] * Wl[f * 2 + 1]; }
        float u0 = l0 + (tgt == 1 ? 1.f : 0.f);
        float u1 = l1 + (tgt == 0 ? 1.f : 0.f);
        float mm = fmaxf(u0, u1);
        float lse = mm + logf(expf(u0 - mm) + expf(u1 - mm));
        float sy = tgt ? l1 : l0;
        loss += lse - sy;
    }
    out[OUT_LOSS] = loss * (1.f / 16.f);
}

// ---------------- launch ----------------
extern "C" void kernel_launch(void* const* d_in, const int* in_sizes, int n_in,
                              void* d_out, int out_size) {
    const float* x = (const float*)d_in[0];
    const void* ei = d_in[1];
    const float* ew = (const float*)d_in[2];
    const int* label = (const int*)d_in[3];
    const float* W1 = (const float*)d_in[4];
    const float* b1 = (const float*)d_in[5];
    const float* ln1w = (const float*)d_in[6];
    const float* ln1b = (const float*)d_in[7];
    const float* W2 = (const float*)d_in[8];
    const float* b2 = (const float*)d_in[9];
    const float* ln2w = (const float*)d_in[10];
    const float* ln2b = (const float*)d_in[11];
    const float* Wf = (const float*)d_in[12];
    const float* bf = (const float*)d_in[13];
    const float* Wt = (const float*)d_in[14];
    const float* bt = (const float*)d_in[15];
    const float* Ws = (const float*)d_in[16];
    const float* bs = (const float*)d_in[17];
    const float* Wc = (const float*)d_in[18];
    const float* bc = (const float*)d_in[19];
    const float* Wcls = (const float*)d_in[20];
    const float* bcls = (const float*)d_in[21];
    const float* Wcell = (const float*)d_in[22];
    const float* bcell = (const float*)d_in[23];
    float* out = (float*)d_out;

    int nb_scan = (NN + 1023) / 1024;        // 98
    int nb_node = (NN + 127) / 128;          // 782
    int nb_aggc = (NN + 7) / 8;              // 12500

    k_prepmm<<<NB_EDGE + NB_NODE, 256>>>(ei, ew, x, W1);
    k_scan1<<<nb_scan, 1024>>>();
    k_scan3<<<nb_scan, 1024>>>(nb_scan);
    k_scatter<<<NB_EDGE, 256>>>(ew);

    // layer 1
    k_aggc<<<nb_aggc, 256>>>(b1);
    k_post1mm<<<nb_node, 128>>>(ln1w, ln1b, W2);
    // layer 2
    k_aggc<<<nb_aggc, 256>>>(b2);
    k_post2<<<nb_node, 128>>>(ln2w, ln2b, Wf, bf, Wt, bt, Ws, bs, Wc, bc,
                              out + OUT_X3);

    // softmax + pool (fused finalize)
    k_softpool<<<NB_SP, 256>>>();

    // topk (+A write) and tail (+final)
    k_topk1<<<NB_TK, 1024>>>(out + OUT_A);
    k_topk2<<<1, 1024>>>(Wcls, bcls, Wcell, bcell, label, out);
}

// round 16
// speedup vs baseline: 1.0755x; 1.0375x over previous
#include <cuda_runtime.h>
#include <math.h>

#define NN 100000
#define NE 2000000
#define INC 30
#define HID 40
#define D1 20
#define D2 10
#define NCLS 3
#define NB_SP 128   // softpool blocks
#define NB_TK 128   // topk stage-1 blocks
#define NB_EDGE ((NE + 255) / 256)   // 7813
#define NB_NODE ((NN + 255) / 256)   // 391

// out layout: logits[3], Y_prob[3], Y_hat[1], A[NN], x3[NN*D1], cell_loss[1]
#define OUT_A 7
#define OUT_X3 (7 + NN)
#define OUT_LOSS (7 + NN + NN * D1)

// ---------------- scratch ----------------
__device__ __align__(16) float g_h[NN * HID];      // holds h' = h * dinv
__device__ __align__(16) float g_agg[NN * HID];
__device__ __align__(16) float g_x3[NN * D1];
__device__ float g_a[NN];
__device__ unsigned long long g_dc[NN];    // packed cnt<<40 | deg*2^28 (zero on entry; re-zeroed in scan3)
__device__ float g_dinv[NN];
__device__ int   g_pref[NN];
__device__ int   g_bsum[128];
__device__ int   g_rowstart[NN + 1];
__device__ unsigned long long g_sdr[NE];   // packed s | d<<17 | rank<<34
__device__ unsigned long long g_csr[NE];
__device__ float g_bm[NB_SP];
__device__ float g_bs[NB_SP];
__device__ float g_bp[NB_SP * D1];
__device__ float g_gmax;
__device__ float g_denom;
__device__ float g_pooled[D1];
__device__ float g_cand_v[2 * NB_TK * 8];
__device__ int   g_cand_i[2 * NB_TK * 8];
__device__ unsigned int g_done;            // zero on entry; re-zeroed in topk2

// ---------------- helpers ----------------
__device__ __forceinline__ float selu_f(float x) {
    const float sc = 1.0507009873554805f, al = 1.6732632423543772f;
    return x > 0.f ? sc * x : sc * al * expm1f(x);
}
__device__ __forceinline__ int clampn(int v) {
    return v < 0 ? 0 : (v >= NN ? NN - 1 : v);
}

// ---------------- kernels ----------------
// edge prep only: single packed atomic, write (s,d,rank)
__global__ void k_prep(const void* __restrict__ eiv, const float* __restrict__ ew) {
    __shared__ int any_nz;
    const int* ei32 = (const int*)eiv;
    if (threadIdx.x == 0) any_nz = 0;
    __syncthreads();
    if (ei32[2 * threadIdx.x + 1] != 0) atomicOr(&any_nz, 1);
    __syncthreads();
    bool is64 = (any_nz == 0);
    int e = blockIdx.x * 256 + threadIdx.x;
    if (e >= NE) return;
    int s, d;
    if (is64) {
        const long long* ei = (const long long*)eiv;
        s = (int)ei[e]; d = (int)ei[NE + e];
    } else {
        s = ei32[e]; d = ei32[NE + e];
    }
    s = clampn(s); d = clampn(d);
    unsigned long long fx = (unsigned long long)(ew[e] * 268435456.0f + 0.5f);
    unsigned long long old = atomicAdd(&g_dc[d], (1ULL << 40) | fx);
    unsigned long long rank = old >> 40;
    g_sdr[e] = (unsigned long long)(unsigned)s |
               ((unsigned long long)(unsigned)d << 17) | (rank << 34);
}

// block-local exclusive scan of counts
__global__ void k_scan1() {
    __shared__ int sm[1024];
    int t = threadIdx.x;
    int gid = blockIdx.x * 1024 + t;
    int x = (gid < NN) ? (int)(g_dc[gid] >> 40) : 0;
    sm[t] = x; __syncthreads();
    for (int off = 1; off < 1024; off <<= 1) {
        int v = (t >= off) ? sm[t - off] : 0;
        __syncthreads();
        sm[t] += v;
        __syncthreads();
    }
    if (gid < NN) g_pref[gid] = sm[t] - x;
    if (t == 1023) g_bsum[blockIdx.x] = sm[1023];
}

// add block offsets (serial 98-sum by t0) + rowstart/dinv; reset g_dc
__global__ void k_scan3(int nblk) {
    __shared__ int sb[128];
    __shared__ int soff;
    int t = threadIdx.x;
    if (t < 128) sb[t] = (t < nblk) ? g_bsum[t] : 0;
    __syncthreads();
    if (t == 0) {
        int s = 0;
        for (int j = 0; j < blockIdx.x; j++) s += sb[j];
        soff = s;
    }
    __syncthreads();
    int gid = blockIdx.x * 1024 + t;
    if (gid < NN) {
        g_rowstart[gid] = g_pref[gid] + soff;
        unsigned long long dc = g_dc[gid];
        float deg = (float)(dc & ((1ULL << 40) - 1ULL)) * (1.0f / 268435456.0f);
        g_dinv[gid] = rsqrtf(deg + 1.0f);
        g_dc[gid] = 0ULL;   // reset for next graph replay
    }
    if (gid == 0) g_rowstart[NN] = NE;
}

// blocks [0, NB_EDGE): build CSR entries (src, ew) — pure streaming, no
//   random reads (dinv factored into h' and aggc tail).
// blocks [NB_EDGE, ...): h' = (x @ W1) * dinv[n]  (dinv now available)
__global__ void k_scattermm(const float* __restrict__ ew, const float* __restrict__ X,
                            const float* __restrict__ W) {
    if (blockIdx.x < NB_EDGE) {
        int e = blockIdx.x * 256 + threadIdx.x;
        if (e >= NE) return;
        unsigned long long ent = __ldg(&g_sdr[e]);
        int s = (int)(ent & 0x1FFFFULL);
        int d = (int)((ent >> 17) & 0x1FFFFULL);
        int rank = (int)(ent >> 34);
        float w = __ldg(ew + e);
        int pos = g_rowstart[d] + rank;
        g_csr[pos] = ((unsigned long long)__float_as_uint(w) << 32) | (unsigned int)s;
    } else {
        __shared__ float sW[INC * HID];
        for (int i = threadIdx.x; i < INC * HID; i += 256) sW[i] = W[i];
        __syncthreads();
        int n = (blockIdx.x - NB_EDGE) * 256 + threadIdx.x;
        if (n >= NN) return;
        float acc[HID];
#pragma unroll
        for (int o = 0; o < HID; o++) acc[o] = 0.f;
        const float* xr = X + (long)n * INC;
#pragma unroll
        for (int k = 0; k < INC; k++) {
            float xv = __ldg(xr + k);
#pragma unroll
            for (int o = 0; o < HID; o++) acc[o] += xv * sW[k * HID + o];
        }
        float di = g_dinv[n];
        float* yr = g_h + (long)n * HID;
#pragma unroll
        for (int o = 0; o < HID; o++) yr[o] = acc[o] * di;
    }
}

// CSR aggregation: warp per node, 30 lanes = 3 edges x 10 chunks.
// Unroll-2 (MLP=2) + dual csr prefetch. h holds h' = h*dinv, csr weight = ew:
// agg[n] = dinv[n] * ( sum_e ew_e * h'[src_e] + h'[n] ) + b
__global__ void k_aggc(const float* __restrict__ b) {
    int warp = blockIdx.x * 8 + (threadIdx.x >> 5);
    if (warp >= NN) return;
    int lane = threadIdx.x & 31;
    int grp = lane / 10;          // 0..2 active, 3 idle (lanes 30,31)
    int chunk = lane - grp * 10;  // 0..9
    bool act = lane < 30;
    int beg = g_rowstart[warp], end = g_rowstart[warp + 1];
    const float4* h4 = reinterpret_cast<const float4*>(g_h);
    float4 acc = make_float4(0.f, 0.f, 0.f, 0.f);

    int e0 = beg + grp;
    unsigned long long ent0 = (act && e0 < end) ? __ldg(&g_csr[e0]) : 0ULL;
    unsigned long long ent1 = (act && e0 + 3 < end) ? __ldg(&g_csr[e0 + 3]) : 0ULL;
    for (int e = beg; e < end; e += 6) {
        bool v0ok = act && (e + grp) < end;
        bool v1ok = act && (e + 3 + grp) < end;
        unsigned long long cur0 = ent0;
        unsigned long long cur1 = ent1;
        int en0 = e + 6 + grp, en1 = e + 9 + grp;
        ent0 = (act && en0 < end) ? __ldg(&g_csr[en0]) : 0ULL;
        ent1 = (act && en1 < end) ? __ldg(&g_csr[en1]) : 0ULL;
        int s0 = (int)(unsigned int)cur0;
        int s1 = (int)(unsigned int)cur1;
        float w0 = v0ok ? __uint_as_float((unsigned int)(cur0 >> 32)) : 0.f;
        float w1 = v1ok ? __uint_as_float((unsigned int)(cur1 >> 32)) : 0.f;
        float4 v0 = v0ok ? __ldg(h4 + s0 * 10 + chunk) : make_float4(0.f, 0.f, 0.f, 0.f);
        float4 v1 = v1ok ? __ldg(h4 + s1 * 10 + chunk) : make_float4(0.f, 0.f, 0.f, 0.f);
        acc.x += v0.x * w0 + v1.x * w1;
        acc.y += v0.y * w0 + v1.y * w1;
        acc.z += v0.z * w0 + v1.z * w1;
        acc.w += v0.w * w0 + v1.w * w1;
    }
    float rx = acc.x + __shfl_down_sync(0xffffffffu, acc.x, 10)
                     + __shfl_down_sync(0xffffffffu, acc.x, 20);
    float ry = acc.y + __shfl_down_sync(0xffffffffu, acc.y, 10)
                     + __shfl_down_sync(0xffffffffu, acc.y, 20);
    float rz = acc.z + __shfl_down_sync(0xffffffffu, acc.z, 10)
                     + __shfl_down_sync(0xffffffffu, acc.z, 20);
    float rw = acc.w + __shfl_down_sync(0xffffffffu, acc.w, 10)
                     + __shfl_down_sync(0xffffffffu, acc.w, 20);
    if (lane < 10) {
        float di = g_dinv[warp];
        float4 hv = h4[warp * 10 + lane];   // h'
        float4 bv = __ldg(reinterpret_cast<const float4*>(b) + lane);
        float4 r;
        r.x = (rx + hv.x) * di + bv.x;
        r.y = (ry + hv.y) * di + bv.y;
        r.z = (rz + hv.z) * di + bv.z;
        r.w = (rw + hv.w) * di + bv.w;
        reinterpret_cast<float4*>(g_agg)[warp * 10 + lane] = r;
    }
}

// x1 = selu(ln(agg)); h2' = (x1 @ W2) * dinv -> g_h (overwrite)
__global__ void k_post1mm(const float* __restrict__ lw, const float* __restrict__ lb,
                          const float* __restrict__ W2) {
    __shared__ float sW[HID * HID];
    for (int i = threadIdx.x; i < HID * HID; i += blockDim.x) sW[i] = W2[i];
    __syncthreads();
    int n = blockIdx.x * blockDim.x + threadIdx.x;
    if (n >= NN) return;
    float v[HID];
    const float4* ag = reinterpret_cast<const float4*>(g_agg) + n * (HID / 4);
    float s = 0.f;
#pragma unroll
    for (int j = 0; j < HID / 4; j++) {
        float4 a4 = ag[j];
        v[4 * j + 0] = a4.x; v[4 * j + 1] = a4.y;
        v[4 * j + 2] = a4.z; v[4 * j + 3] = a4.w;
        s += a4.x + a4.y + a4.z + a4.w;
    }
    float m = s * (1.f / HID);
    float vs = 0.f;
#pragma unroll
    for (int f = 0; f < HID; f++) { float dd = v[f] - m; vs += dd * dd; }
    float inv = rsqrtf(vs * (1.f / HID) + 1e-5f);
#pragma unroll
    for (int f = 0; f < HID; f++)
        v[f] = selu_f((v[f] - m) * inv * __ldg(lw + f) + __ldg(lb + f));
    float acc[HID];
#pragma unroll
    for (int o = 0; o < HID; o++) acc[o] = 0.f;
#pragma unroll
    for (int k = 0; k < HID; k++) {
        float xv = v[k];
#pragma unroll
        for (int o = 0; o < HID; o++) acc[o] += xv * sW[k * HID + o];
    }
    float di = g_dinv[n];
    float* yr = g_h + (long)n * HID;
#pragma unroll
    for (int o = 0; o < HID; o++) yr[o] = acc[o] * di;
}

// x2 = selu(ln(agg)); x3 = selu(x2@Wf+bf) -> g_x3 + outx3; a = attention score
__global__ void k_post2(const float* __restrict__ lw, const float* __restrict__ lb,
                        const float* __restrict__ Wf, const float* __restrict__ bf,
                        const float* __restrict__ Wt, const float* __restrict__ bt,
                        const float* __restrict__ Ws, const float* __restrict__ bs,
                        const float* __restrict__ Wc, const float* __restrict__ bc,
                        float* __restrict__ outx3) {
    __shared__ float sWf[HID * D1];
    __shared__ float sWt[D1 * D2];
    __shared__ float sWs[D1 * D2];
    __shared__ float sWc[D2];
    __shared__ float sbf[D1], sbt[D2], sbs[D2];
    int t = threadIdx.x;
    for (int i = t; i < HID * D1; i += blockDim.x) sWf[i] = Wf[i];
    for (int i = t; i < D1 * D2; i += blockDim.x) { sWt[i] = Wt[i]; sWs[i] = Ws[i]; }
    if (t < D2) { sWc[t] = Wc[t]; sbt[t] = bt[t]; sbs[t] = bs[t]; }
    if (t < D1) sbf[t] = bf[t];
    __syncthreads();
    int n = blockIdx.x * blockDim.x + t;
    if (n >= NN) return;
    float v[HID];
    const float4* ag = reinterpret_cast<const float4*>(g_agg) + n * (HID / 4);
    float s = 0.f;
#pragma unroll
    for (int j = 0; j < HID / 4; j++) {
        float4 a4 = ag[j];
        v[4 * j + 0] = a4.x; v[4 * j + 1] = a4.y;
        v[4 * j + 2] = a4.z; v[4 * j + 3] = a4.w;
        s += a4.x + a4.y + a4.z + a4.w;
    }
    float m = s * (1.f / HID);
    float vs = 0.f;
#pragma unroll
    for (int f = 0; f < HID; f++) { float dd = v[f] - m; vs += dd * dd; }
    float inv = rsqrtf(vs * (1.f / HID) + 1e-5f);
#pragma unroll
    for (int f = 0; f < HID; f++)
        v[f] = selu_f((v[f] - m) * inv * __ldg(lw + f) + __ldg(lb + f));
    float x3[D1];
#pragma unroll
    for (int o = 0; o < D1; o++) {
        float acc = sbf[o];
#pragma unroll
        for (int k = 0; k < HID; k++) acc += v[k] * sWf[k * D1 + o];
        x3[o] = selu_f(acc);
    }
    float* xo = g_x3 + (long)n * D1;
    float* xo2 = outx3 + (long)n * D1;
#pragma unroll
    for (int o = 0; o < D1; o++) { xo[o] = x3[o]; xo2[o] = x3[o]; }
    float a = __ldg(bc);
#pragma unroll
    for (int j = 0; j < D2; j++) {
        float zt = sbt[j], zs = sbs[j];
#pragma unroll
        for (int k = 0; k < D1; k++) { zt += x3[k] * sWt[k * D2 + j]; zs += x3[k] * sWs[k * D2 + j]; }
        a += tanhf(zt) * (1.f / (1.f + expf(-zs))) * sWc[j];
    }
    g_a[n] = a;
}

// per-block (m, s, p) partials; last block finalizes gmax/denom/pooled
__global__ void k_softpool() {
    __shared__ float sm[256];
    __shared__ float sbp[D1];
    __shared__ bool isLast;
    int t = threadIdx.x;
    float mx = __int_as_float(0xff800000);
    for (int i = blockIdx.x * 256 + t; i < NN; i += NB_SP * 256)
        mx = fmaxf(mx, g_a[i]);
    sm[t] = mx; __syncthreads();
    for (int st = 128; st > 0; st >>= 1) {
        if (t < st) sm[t] = fmaxf(sm[t], sm[t + st]);
        __syncthreads();
    }
    float mb = sm[0];
    __syncthreads();
    float ssum = 0.f;
    float acc[D1];
#pragma unroll
    for (int f = 0; f < D1; f++) acc[f] = 0.f;
    for (int i = blockIdx.x * 256 + t; i < NN; i += NB_SP * 256) {
        float w = expf(g_a[i] - mb);
        ssum += w;
        const float4* xr = reinterpret_cast<const float4*>(g_x3) + i * (D1 / 4);
#pragma unroll
        for (int j = 0; j < D1 / 4; j++) {
            float4 t4 = __ldg(xr + j);
            acc[4 * j + 0] += w * t4.x; acc[4 * j + 1] += w * t4.y;
            acc[4 * j + 2] += w * t4.z; acc[4 * j + 3] += w * t4.w;
        }
    }
    sm[t] = ssum; __syncthreads();
    for (int st = 128; st > 0; st >>= 1) {
        if (t < st) sm[t] += sm[t + st];
        __syncthreads();
    }
    if (t == 0) { g_bm[blockIdx.x] = mb; g_bs[blockIdx.x] = sm[0]; }
    if (t < D1) sbp[t] = 0.f;
    __syncthreads();
#pragma unroll
    for (int f = 0; f < D1; f++) {
        float vv = acc[f];
        for (int off = 16; off; off >>= 1) vv += __shfl_down_sync(0xffffffffu, vv, off);
        if ((t & 31) == 0) atomicAdd(&sbp[f], vv);
    }
    __syncthreads();
    if (t < D1) g_bp[blockIdx.x * D1 + t] = sbp[t];
    __threadfence();
    if (t == 0) {
        unsigned int prev = atomicAdd(&g_done, 1u);
        isLast = (prev == NB_SP - 1);
    }
    __syncthreads();
    if (!isLast) return;
    __threadfence();
    float mt = (t < NB_SP) ? g_bm[t] : __int_as_float(0xff800000);
    sm[t] = mt; __syncthreads();
    for (int st = 128; st > 0; st >>= 1) {
        if (t < st) sm[t] = fmaxf(sm[t], sm[t + st]);
        __syncthreads();
    }
    float M = sm[0];
    __syncthreads();
    float scale = (t < NB_SP) ? expf(mt - M) : 0.f;
    sm[t] = (t < NB_SP) ? g_bs[t] * scale : 0.f;
    __syncthreads();
    for (int st = 128; st > 0; st >>= 1) {
        if (t < st) sm[t] += sm[t + st];
        __syncthreads();
    }
    float denom = sm[0];
    if (t == 0) { g_gmax = M; g_denom = denom; }
    __syncthreads();
    for (int f = 0; f < D1; f++) {
        sm[t] = (t < NB_SP) ? g_bp[t * D1 + f] * scale : 0.f;
        __syncthreads();
        for (int st = 128; st > 0; st >>= 1) {
            if (t < st) sm[t] += sm[t + st];
            __syncthreads();
        }
        if (t == 0) g_pooled[f] = sm[0] / denom;
        __syncthreads();
    }
}

// stage-1 topk: each block = 1024 contiguous elements; also writes softmax A
__global__ void k_topk1(float* __restrict__ outA) {
    __shared__ float sv[1024];
    __shared__ int si[1024];
    int t = threadIdx.x;
    int gid = blockIdx.x * 1024 + t;
    bool valid = gid < NN;
    float a = valid ? g_a[gid] : 0.f;
    if (valid) outA[gid] = expf(a - g_gmax) / g_denom;
    float vt = valid ? a : __int_as_float(0xff800000);
    float vb = valid ? a : __int_as_float(0x7f800000);
    int myi = valid ? gid : 0x7fffffff;
    for (int pass = 0; pass < 8; pass++) {
        sv[t] = vt; si[t] = myi; __syncthreads();
        for (int st = 512; st > 0; st >>= 1) {
            if (t < st) {
                float v2 = sv[t + st]; int i2 = si[t + st];
                if (v2 > sv[t] || (v2 == sv[t] && i2 < si[t])) { sv[t] = v2; si[t] = i2; }
            }
            __syncthreads();
        }
        if (t == 0) {
            g_cand_v[blockIdx.x * 8 + pass] = sv[0];
            g_cand_i[blockIdx.x * 8 + pass] = si[0];
        }
        if (myi == si[0]) vt = __int_as_float(0xff800000);
        __syncthreads();
    }
    for (int pass = 0; pass < 8; pass++) {
        sv[t] = vb; si[t] = myi; __syncthreads();
        for (int st = 512; st > 0; st >>= 1) {
            if (t < st) {
                float v2 = sv[t + st]; int i2 = si[t + st];
                if (v2 < sv[t] || (v2 == sv[t] && i2 < si[t])) { sv[t] = v2; si[t] = i2; }
            }
            __syncthreads();
        }
        if (t == 0) {
            g_cand_v[NB_TK * 8 + blockIdx.x * 8 + pass] = sv[0];
            g_cand_i[NB_TK * 8 + blockIdx.x * 8 + pass] = si[0];
        }
        if (myi == si[0]) vb = __int_as_float(0x7f800000);
        __syncthreads();
    }
}

// stage-2 merge + final tail math; resets g_done for next replay
__global__ void k_topk2(const float* __restrict__ Wcls, const float* __restrict__ bcls,
                        const float* __restrict__ Wcell, const float* __restrict__ bcell,
                        const int* __restrict__ labelp, float* __restrict__ out) {
    __shared__ float sv[1024];
    __shared__ int si[1024];
    __shared__ int ssel[16];
    int t = threadIdx.x;
    float vt = g_cand_v[t];
    int it = g_cand_i[t];
    for (int pass = 0; pass < 8; pass++) {
        sv[t] = vt; si[t] = it; __syncthreads();
        for (int st = 512; st > 0; st >>= 1) {
            if (t < st) {
                float v2 = sv[t + st]; int i2 = si[t + st];
                if (v2 > sv[t] || (v2 == sv[t] && i2 < si[t])) { sv[t] = v2; si[t] = i2; }
            }
            __syncthreads();
        }
        if (t == 0) ssel[pass] = si[0];
        if (it == si[0]) vt = __int_as_float(0xff800000);
        __syncthreads();
    }
    float vb = g_cand_v[NB_TK * 8 + t];
    int ib = g_cand_i[NB_TK * 8 + t];
    for (int pass = 0; pass < 8; pass++) {
        sv[t] = vb; si[t] = ib; __syncthreads();
        for (int st = 512; st > 0; st >>= 1) {
            if (t < st) {
                float v2 = sv[t + st]; int i2 = si[t + st];
                if (v2 < sv[t] || (v2 == sv[t] && i2 < si[t])) { sv[t] = v2; si[t] = i2; }
            }
            __syncthreads();
        }
        if (t == 0) ssel[8 + pass] = si[0];
        if (ib == si[0]) vb = __int_as_float(0x7f800000);
        __syncthreads();
    }
    if (t != 0) return;
    g_done = 0u;  // reset for next graph replay
    float logits[NCLS];
#pragma unroll
    for (int c = 0; c < NCLS; c++) {
        float s = bcls[c];
#pragma unroll
        for (int f = 0; f < D1; f++) s += g_pooled[f] * Wcls[f * NCLS + c];
        logits[c] = s;
    }
    float mx = fmaxf(logits[0], fmaxf(logits[1], logits[2]));
    float e0 = expf(logits[0] - mx), e1 = expf(logits[1] - mx), e2 = expf(logits[2] - mx);
    float es = e0 + e1 + e2;
    int yhat = 0;
    if (logits[1] > logits[yhat]) yhat = 1;
    if (logits[2] > logits[yhat]) yhat = 2;
    out[0] = logits[0]; out[1] = logits[1]; out[2] = logits[2];
    out[3] = e0 / es; out[4] = e1 / es; out[5] = e2 / es;
    out[6] = (float)yhat;
    int label = labelp[0];
    if (label < 0) label = 0;
    if (label >= NCLS) label = NCLS - 1;
    const float* Wl = Wcell + label * D1 * 2;
    const float* bl = bcell + label * 2;
    float loss = 0.f;
    for (int i = 0; i < 16; i++) {
        int node = ssel[i];
        if (node < 0 || node >= NN) node = 0;
        int tgt = (i < 8) ? 1 : 0;
        const float* xr = g_x3 + (long)node * D1;
        float l0 = bl[0], l1 = bl[1];
#pragma unroll
        for (int f = 0; f < D1; f++) { l0 += xr[f] * Wl[f * 2]; l1 += xr[f] * Wl[f * 2 + 1]; }
        float u0 = l0 + (tgt == 1 ? 1.f : 0.f);
        float u1 = l1 + (tgt == 0 ? 1.f : 0.f);
        float mm = fmaxf(u0, u1);
        float lse = mm + logf(expf(u0 - mm) + expf(u1 - mm));
        float sy = tgt ? l1 : l0;
        loss += lse - sy;
    }
    out[OUT_LOSS] = loss * (1.f / 16.f);
}

// ---------------- launch ----------------
extern "C" void kernel_launch(void* const* d_in, const int* in_sizes, int n_in,
                              void* d_out, int out_size) {
    const float* x = (const float*)d_in[0];
    const void* ei = d_in[1];
    const float* ew = (const float*)d_in[2];
    const int* label = (const int*)d_in[3];
    const float* W1 = (const float*)d_in[4];
    const float* b1 = (const float*)d_in[5];
    const float* ln1w = (const float*)d_in[6];
    const float* ln1b = (const float*)d_in[7];
    const float* W2 = (const float*)d_in[8];
    const float* b2 = (const float*)d_in[9];
    const float* ln2w = (const float*)d_in[10];
    const float* ln2b = (const float*)d_in[11];
    const float* Wf = (const float*)d_in[12];
    const float* bf = (const float*)d_in[13];
    const float* Wt = (const float*)d_in[14];
    const float* bt = (const float*)d_in[15];
    const float* Ws = (const float*)d_in[16];
    const float* bs = (const float*)d_in[17];
    const float* Wc = (const float*)d_in[18];
    const float* bc = (const float*)d_in[19];
    const float* Wcls = (const float*)d_in[20];
    const float* bcls = (const float*)d_in[21];
    const float* Wcell = (const float*)d_in[22];
    const float* bcell = (const float*)d_in[23];
    float* out = (float*)d_out;

    int nb_scan = (NN + 1023) / 1024;        // 98
    int nb_node = (NN + 127) / 128;          // 782
    int nb_aggc = (NN + 7) / 8;              // 12500

    k_prep<<<NB_EDGE, 256>>>(ei, ew);
    k_scan1<<<nb_scan, 1024>>>();
    k_scan3<<<nb_scan, 1024>>>(nb_scan);
    k_scattermm<<<NB_EDGE + NB_NODE, 256>>>(ew, x, W1);

    // layer 1
    k_aggc<<<nb_aggc, 256>>>(b1);
    k_post1mm<<<nb_node, 128>>>(ln1w, ln1b, W2);
    // layer 2
    k_aggc<<<nb_aggc, 256>>>(b2);
    k_post2<<<nb_node, 128>>>(ln2w, ln2b, Wf, bf, Wt, bt, Ws, bs, Wc, bc,
                              out + OUT_X3);

    // softmax + pool (fused finalize)
    k_softpool<<<NB_SP, 256>>>();

    // topk (+A write) and tail (+final)
    k_topk1<<<NB_TK, 1024>>>(out + OUT_A);
    k_topk2<<<1, 1024>>>(Wcls, bcls, Wcell, bcell, label, out);
}